// round 12
// baseline (speedup 1.0000x reference)
#include <cuda_runtime.h>
#include <cuda_fp16.h>
#include <cstdint>
#include <cstddef>

#define N_NODES 100000
#define N_EDGES 100000
#define NNZ     3200000
#define D_IN    512
#define D_HID   16
#define N_CLS   7
#define LOG2E   1.4426950408889634f
#define FULLM   0xffffffffu

// ---------------- scratch (device globals) ---------------------------------
__device__ __align__(128) __half g_hu1h[(size_t)N_NODES * 16]; // L1 node rows: h*u fp16 (32B)
__device__ float  g_u1[N_NODES];                               // u fp32
__device__ __align__(128) __half g_e1h[(size_t)N_EDGES * 16];  // L1 edge rows: e fp16 (32B)
__device__ float  g_t2e1[N_EDGES];                             // (e.a2hi)*log2e fp32
__device__ __align__(128) __half g_hu2h[(size_t)N_NODES * 8];  // L2 node rows: [h2*u (7), u] (16B)
__device__ __align__(128) __half g_e2h[(size_t)N_EDGES * 8];   // L2 edge rows: [e2 (7), t2*log2e] (16B)
__device__ float  g_t1[N_NODES];                               // (h.a2lo)*log2e
__device__ int    g_eoff[N_EDGES + 1];
__device__ int    g_cnt[N_NODES];
__device__ int    g_noff[N_NODES + 1];
__device__ int    g_cur[N_NODES];
__device__ int    g_pedge[NNZ];
__device__ int    g_bsum[128];
__device__ int    g_bpre[128];

__device__ __forceinline__ float lrelu(float v) { return v > 0.f ? v : 0.2f * v; }

__device__ __forceinline__ unsigned int f2tf32(float x) {
    unsigned int r;
    asm("cvt.rna.tf32.f32 %0, %1;" : "=r"(r) : "f"(x));
    return r;
}
__device__ __forceinline__ void acc8(const uint4& v, float* acc, float w) {
    float2 f0 = __half22float2(*(const __half2*)&v.x);
    float2 f1 = __half22float2(*(const __half2*)&v.y);
    float2 f2 = __half22float2(*(const __half2*)&v.z);
    float2 f3 = __half22float2(*(const __half2*)&v.w);
    acc[0] += w * f0.x; acc[1] += w * f0.y;
    acc[2] += w * f1.x; acc[3] += w * f1.y;
    acc[4] += w * f2.x; acc[5] += w * f2.y;
    acc[6] += w * f3.x; acc[7] += w * f3.y;
}
__device__ __forceinline__ void add8(const uint4& v, float* acc) {
    float2 f0 = __half22float2(*(const __half2*)&v.x);
    float2 f1 = __half22float2(*(const __half2*)&v.y);
    float2 f2 = __half22float2(*(const __half2*)&v.z);
    float2 f3 = __half22float2(*(const __half2*)&v.w);
    acc[0] += f0.x; acc[1] += f0.y;
    acc[2] += f1.x; acc[3] += f1.y;
    acc[4] += f2.x; acc[5] += f2.y;
    acc[6] += f3.x; acc[7] += f3.y;
}
__device__ __forceinline__ uint4 pack8(const float* e) {
    __half2 p[4];
    p[0] = __float22half2_rn(make_float2(e[0], e[1]));
    p[1] = __float22half2_rn(make_float2(e[2], e[3]));
    p[2] = __float22half2_rn(make_float2(e[4], e[5]));
    p[3] = __float22half2_rn(make_float2(e[6], e[7]));
    return *(uint4*)p;
}

// ---------------- k_zero ----------------------------------------------------
__global__ void k_zero()
{
    int n = blockIdx.x * blockDim.x + threadIdx.x;
    if (n < N_NODES) g_cnt[n] = 0;
}

// ---------------- edge offsets ---------------------------------------------
__global__ void k_eoff(const int* __restrict__ edge_idx)
{
    int e = blockIdx.x * blockDim.x + threadIdx.x;
    if (e >= N_EDGES) return;
    int lo = 0, hi = NNZ;
    while (lo < hi) {
        int m = (lo + hi) >> 1;
        if (__ldg(edge_idx + m) < e) lo = m + 1; else hi = m;
    }
    g_eoff[e] = lo;
    if (e == 0) g_eoff[N_EDGES] = NNZ;
}

// ---------------- node CSR build -------------------------------------------
__global__ void k_count(const int4* __restrict__ node_idx4)
{
    int i = blockIdx.x * blockDim.x + threadIdx.x;
    if (i >= NNZ / 4) return;
    int4 v = node_idx4[i];
    atomicAdd(&g_cnt[v.x], 1);
    atomicAdd(&g_cnt[v.y], 1);
    atomicAdd(&g_cnt[v.z], 1);
    atomicAdd(&g_cnt[v.w], 1);
}
__global__ void k_scan1()
{
    __shared__ int sp[1024];
    int t = threadIdx.x, b = blockIdx.x;
    int idx = b * 1000 + t;
    int v = (t < 1000) ? g_cnt[idx] : 0;
    sp[t] = v;
    __syncthreads();
    for (int o = 1; o < 1024; o <<= 1) {
        int u = (t >= o) ? sp[t - o] : 0;
        __syncthreads();
        sp[t] += u;
        __syncthreads();
    }
    if (t < 1000) g_noff[idx] = sp[t] - v;
    if (t == 1023) g_bsum[b] = sp[1023];
}
__global__ void k_scan2()
{
    __shared__ int sp[128];
    int t = threadIdx.x;
    int v = (t < 100) ? g_bsum[t] : 0;
    sp[t] = v;
    __syncthreads();
    for (int o = 1; o < 128; o <<= 1) {
        int u = (t >= o) ? sp[t - o] : 0;
        __syncthreads();
        sp[t] += u;
        __syncthreads();
    }
    if (t < 100) g_bpre[t] = sp[t] - v;
}
__global__ void k_scan3()
{
    int t = threadIdx.x, b = blockIdx.x;
    int idx = b * 1000 + t;
    if (t < 1000) {
        int o = g_noff[idx] + g_bpre[b];
        g_noff[idx] = o;
        g_cur[idx] = o;
    }
    if (idx == 0) g_noff[N_NODES] = NNZ;
}
__global__ void k_scatter(const int4* __restrict__ node_idx4, const int4* __restrict__ edge_idx4)
{
    int i = blockIdx.x * blockDim.x + threadIdx.x;
    if (i >= NNZ / 4) return;
    int4 nd = node_idx4[i];
    int4 ed = edge_idx4[i];
    g_pedge[atomicAdd(&g_cur[nd.x], 1)] = ed.x;
    g_pedge[atomicAdd(&g_cur[nd.y], 1)] = ed.y;
    g_pedge[atomicAdd(&g_cur[nd.z], 1)] = ed.z;
    g_pedge[atomicAdd(&g_cur[nd.w], 1)] = ed.w;
}

// ---------------- GEMM1: tf32 tensor-core mma (m16n8k8) --------------------
// block 256 thr / 8 warps; tile 128 rows x 16 cols; warp w -> rows w*16..+15.
__global__ void k_gemm1(const float* __restrict__ X, const float* __restrict__ W,
                        const float* __restrict__ a1, const float* __restrict__ a2lo)
{
    __shared__ __align__(16) float sX[128 * 65];   // tf32-valued fp32; reused as D stage (stride 17)
    __shared__ __align__(16) float sW[64 * 16];
    const int t = threadIdx.x;
    const int lane = t & 31;
    const int w = t >> 5;
    const int nbase = blockIdx.x * 128;
    const int wrow = w * 16;
    const int g = lane >> 2, c4 = lane & 3;

    float d[2][4] = {{0.f, 0.f, 0.f, 0.f}, {0.f, 0.f, 0.f, 0.f}};

    for (int ck = 0; ck < D_IN; ck += 64) {
        // load X tile 128x64 fp32 -> tf32 -> smem
        for (int q = t; q < 128 * 16; q += 256) {
            int row = q >> 4, fc = q & 15;
            int n = nbase + row;
            float4 v = make_float4(0.f, 0.f, 0.f, 0.f);
            if (n < N_NODES) v = *(const float4*)(X + (size_t)n * D_IN + ck + fc * 4);
            int b = row * 65 + fc * 4;
            sX[b]     = __uint_as_float(f2tf32(v.x));
            sX[b + 1] = __uint_as_float(f2tf32(v.y));
            sX[b + 2] = __uint_as_float(f2tf32(v.z));
            sX[b + 3] = __uint_as_float(f2tf32(v.w));
        }
        // load W tile 64x16 -> tf32 -> smem
        for (int q = t; q < 1024; q += 256) {
            float wv = __ldg(W + (ck + (q >> 4)) * 16 + (q & 15));
            sW[q] = __uint_as_float(f2tf32(wv));
        }
        __syncthreads();
#pragma unroll
        for (int ks = 0; ks < 8; ks++) {
            int k0 = ks * 8;
            unsigned int a0 = __float_as_uint(sX[(wrow + g) * 65 + k0 + c4]);
            unsigned int a1r = __float_as_uint(sX[(wrow + g + 8) * 65 + k0 + c4]);
            unsigned int a2 = __float_as_uint(sX[(wrow + g) * 65 + k0 + c4 + 4]);
            unsigned int a3 = __float_as_uint(sX[(wrow + g + 8) * 65 + k0 + c4 + 4]);
#pragma unroll
            for (int nt = 0; nt < 2; nt++) {
                unsigned int b0 = __float_as_uint(sW[(k0 + c4) * 16 + nt * 8 + g]);
                unsigned int b1 = __float_as_uint(sW[(k0 + c4 + 4) * 16 + nt * 8 + g]);
                asm volatile(
                    "mma.sync.aligned.m16n8k8.row.col.f32.tf32.tf32.f32 "
                    "{%0,%1,%2,%3}, {%4,%5,%6,%7}, {%8,%9}, {%0,%1,%2,%3};"
                    : "+f"(d[nt][0]), "+f"(d[nt][1]), "+f"(d[nt][2]), "+f"(d[nt][3])
                    : "r"(a0), "r"(a1r), "r"(a2), "r"(a3), "r"(b0), "r"(b1));
            }
        }
        __syncthreads();
    }

    // stage D (16x16 per warp) into smem, stride 17
#pragma unroll
    for (int nt = 0; nt < 2; nt++) {
        sX[(wrow + g) * 17 + nt * 8 + 2 * c4]     = d[nt][0];
        sX[(wrow + g) * 17 + nt * 8 + 2 * c4 + 1] = d[nt][1];
        sX[(wrow + g + 8) * 17 + nt * 8 + 2 * c4]     = d[nt][2];
        sX[(wrow + g + 8) * 17 + nt * 8 + 2 * c4 + 1] = d[nt][3];
    }
    __syncthreads();
    // epilogue: one thread per row
    if (t < 128) {
        int n = nbase + t;
        if (n < N_NODES) {
            float hv[16];
            float uu = 0.f, tt = 0.f;
#pragma unroll
            for (int j = 0; j < D_HID; j++) {
                hv[j] = sX[t * 17 + j];
                uu += hv[j] * __ldg(a1 + j);
                tt += hv[j] * __ldg(a2lo + j);
            }
            float u = exp2f(lrelu(uu * LOG2E));
            float e0[8], e1[8];
#pragma unroll
            for (int j = 0; j < 8; j++) { e0[j] = hv[j] * u; e1[j] = hv[8 + j] * u; }
            __half* dst = g_hu1h + (size_t)n * 16;
            *(uint4*)dst = pack8(e0);
            *(uint4*)(dst + 8) = pack8(e1);
            g_u1[n] = u;
            g_t1[n] = tt * LOG2E;
        }
    }
}

// ---------------- phase 1, layer 1: 8-lane group per edge, unroll x4 -------
__global__ void k_phase1_l1(const int* __restrict__ node_idx, const float* __restrict__ a2hi)
{
    int gid = (blockIdx.x * blockDim.x + threadIdx.x) >> 3;
    if (gid >= N_EDGES) return;
    const int lane = threadIdx.x & 31;
    const int ll = lane & 7;
    const int r = ll & 1;
    int s = __ldg(g_eoff + gid), epos = __ldg(g_eoff + gid + 1);

    float acc[8];
#pragma unroll
    for (int k = 0; k < 8; k++) acc[k] = 0.f;
    float usum = 0.f;

    int i = s + (ll >> 1);
    for (; i + 12 < epos; i += 16) {
        int nd0 = __ldg(node_idx + i);
        int nd1 = __ldg(node_idx + i + 4);
        int nd2 = __ldg(node_idx + i + 8);
        int nd3 = __ldg(node_idx + i + 12);
        uint4 v0 = *((const uint4*)(g_hu1h + (size_t)nd0 * 16) + r);
        uint4 v1 = *((const uint4*)(g_hu1h + (size_t)nd1 * 16) + r);
        uint4 v2 = *((const uint4*)(g_hu1h + (size_t)nd2 * 16) + r);
        uint4 v3 = *((const uint4*)(g_hu1h + (size_t)nd3 * 16) + r);
        add8(v0, acc); add8(v1, acc); add8(v2, acc); add8(v3, acc);
        if (r == 0) usum += __ldg(g_u1 + nd0) + __ldg(g_u1 + nd1)
                          + __ldg(g_u1 + nd2) + __ldg(g_u1 + nd3);
    }
    for (; i < epos; i += 4) {
        int nd = __ldg(node_idx + i);
        uint4 v = *((const uint4*)(g_hu1h + (size_t)nd * 16) + r);
        add8(v, acc);
        if (r == 0) usum += __ldg(g_u1 + nd);
    }
#pragma unroll
    for (int o = 4; o >= 2; o >>= 1)
#pragma unroll
        for (int k = 0; k < 8; k++)
            acc[k] += __shfl_down_sync(FULLM, acc[k], o, 8);
    usum += __shfl_down_sync(FULLM, usum, 4, 8);
    usum += __shfl_down_sync(FULLM, usum, 2, 8);
    usum = __shfl_sync(FULLM, usum, 0, 8);
    float inv = 1.f / (usum + 1e-9f);

    float t2p = 0.f;
    if (ll < 2) {
        float e8[8];
#pragma unroll
        for (int k = 0; k < 8; k++) {
            e8[k] = acc[k] * inv;
            t2p += e8[k] * __ldg(a2hi + r * 8 + k);
        }
        *((uint4*)(g_e1h + (size_t)gid * 16) + r) = pack8(e8);
    }
    t2p += __shfl_xor_sync(FULLM, t2p, 1);
    if (ll == 0) g_t2e1[gid] = t2p * LOG2E;
}

// ---------------- phase 2, layer 1 + fused gemm2 epilogue, unroll x4 -------
__global__ void k_phase2_l1(float* __restrict__ H1out, const float* __restrict__ W2,
                            const float* __restrict__ a1, const float* __restrict__ a2lo)
{
    int gid = (blockIdx.x * blockDim.x + threadIdx.x) >> 3;
    if (gid >= N_NODES) return;
    const int lane = threadIdx.x & 31;
    const int ll = lane & 7;
    const int r = ll & 1;
    int s = __ldg(g_noff + gid), e = __ldg(g_noff + gid + 1);
    float t1n = __ldg(g_t1 + gid);

    float acc[8];
#pragma unroll
    for (int k = 0; k < 8; k++) acc[k] = 0.f;
    float wsum = 0.f;

    int i = s + (ll >> 1);
    for (; i + 12 < e; i += 16) {
        int ed0 = __ldg(g_pedge + i);
        int ed1 = __ldg(g_pedge + i + 4);
        int ed2 = __ldg(g_pedge + i + 8);
        int ed3 = __ldg(g_pedge + i + 12);
        float t20 = __ldg(g_t2e1 + ed0);
        float t21 = __ldg(g_t2e1 + ed1);
        float t22 = __ldg(g_t2e1 + ed2);
        float t23 = __ldg(g_t2e1 + ed3);
        uint4 v0 = *((const uint4*)(g_e1h + (size_t)ed0 * 16) + r);
        uint4 v1 = *((const uint4*)(g_e1h + (size_t)ed1 * 16) + r);
        uint4 v2 = *((const uint4*)(g_e1h + (size_t)ed2 * 16) + r);
        uint4 v3 = *((const uint4*)(g_e1h + (size_t)ed3 * 16) + r);
        float wv0 = exp2f(lrelu(t1n + t20));
        float wv1 = exp2f(lrelu(t1n + t21));
        float wv2 = exp2f(lrelu(t1n + t22));
        float wv3 = exp2f(lrelu(t1n + t23));
        if (r == 1) wsum += (wv0 + wv1) + (wv2 + wv3);
        acc8(v0, acc, wv0); acc8(v1, acc, wv1);
        acc8(v2, acc, wv2); acc8(v3, acc, wv3);
    }
    for (; i < e; i += 4) {
        int ed = __ldg(g_pedge + i);
        float wv = exp2f(lrelu(t1n + __ldg(g_t2e1 + ed)));
        if (r == 1) wsum += wv;
        uint4 v = *((const uint4*)(g_e1h + (size_t)ed * 16) + r);
        acc8(v, acc, wv);
    }
#pragma unroll
    for (int o = 4; o >= 2; o >>= 1)
#pragma unroll
        for (int k = 0; k < 8; k++)
            acc[k] += __shfl_down_sync(FULLM, acc[k], o, 8);
    wsum += __shfl_down_sync(FULLM, wsum, 4, 8);
    wsum += __shfl_down_sync(FULLM, wsum, 2, 8);
    wsum = __shfl_sync(FULLM, wsum, 1, 8);
    float inv = 1.f / (wsum + 1e-9f);

    float hk[8];
#pragma unroll
    for (int k = 0; k < 8; k++) hk[k] = acc[k] * inv;
    if (ll < 2) {
        *(float4*)(H1out + (size_t)gid * 16 + r * 8) =
            make_float4(hk[0], hk[1], hk[2], hk[3]);
        *(float4*)(H1out + (size_t)gid * 16 + r * 8 + 4) =
            make_float4(hk[4], hk[5], hk[6], hk[7]);
    }

    float h1a = 0.f, h1b = 0.f;
#pragma unroll
    for (int k = 0; k < 8; k++) {
        float t0 = __shfl_sync(FULLM, hk[k], 0, 8);
        float t1v = __shfl_sync(FULLM, hk[k], 1, 8);
        if (ll == k) { h1a = t0; h1b = t1v; }
    }
    float xa = h1a > 0.f ? h1a : expm1f(h1a);
    float xb = h1b > 0.f ? h1b : expm1f(h1b);
    float sarr[N_CLS];
#pragma unroll
    for (int jj = 0; jj < N_CLS; jj++) {
        float p = xa * __ldg(W2 + ll * N_CLS + jj) + xb * __ldg(W2 + (ll + 8) * N_CLS + jj);
        p += __shfl_down_sync(FULLM, p, 4, 8);
        p += __shfl_down_sync(FULLM, p, 2, 8);
        p += __shfl_down_sync(FULLM, p, 1, 8);
        sarr[jj] = p;
    }
    if (ll == 0) {
        float uu = 0.f, tt = 0.f;
#pragma unroll
        for (int jj = 0; jj < N_CLS; jj++) {
            uu += sarr[jj] * __ldg(a1 + jj);
            tt += sarr[jj] * __ldg(a2lo + jj);
        }
        float u = exp2f(lrelu(uu * LOG2E));
        float e8[8];
#pragma unroll
        for (int jj = 0; jj < N_CLS; jj++) e8[jj] = sarr[jj] * u;
        e8[7] = u;
        *(uint4*)(g_hu2h + (size_t)gid * 8) = pack8(e8);
        g_t1[gid] = tt * LOG2E;
    }
}

// ---------------- phase 1, layer 2: unroll x2 ------------------------------
__global__ void k_phase1_l2(const int* __restrict__ node_idx, const float* __restrict__ a2hi)
{
    int gid = (blockIdx.x * blockDim.x + threadIdx.x) >> 3;
    if (gid >= N_EDGES) return;
    const int ll = threadIdx.x & 7;
    int s = __ldg(g_eoff + gid), epos = __ldg(g_eoff + gid + 1);

    float acc[8];
#pragma unroll
    for (int k = 0; k < 8; k++) acc[k] = 0.f;

    int i = s + ll;
    for (; i + 8 < epos; i += 16) {
        int nd0 = __ldg(node_idx + i);
        int nd1 = __ldg(node_idx + i + 8);
        uint4 v0 = *(const uint4*)(g_hu2h + (size_t)nd0 * 8);
        uint4 v1 = *(const uint4*)(g_hu2h + (size_t)nd1 * 8);
        add8(v0, acc);
        add8(v1, acc);
    }
    if (i < epos) {
        int nd = __ldg(node_idx + i);
        uint4 v = *(const uint4*)(g_hu2h + (size_t)nd * 8);
        add8(v, acc);
    }
#pragma unroll
    for (int o = 4; o >= 1; o >>= 1)
#pragma unroll
        for (int k = 0; k < 8; k++)
            acc[k] += __shfl_down_sync(FULLM, acc[k], o, 8);

    if (ll == 0) {
        float inv = 1.f / (acc[7] + 1e-9f);
        float e8[8];
        float t2 = 0.f;
#pragma unroll
        for (int k = 0; k < 7; k++) {
            e8[k] = acc[k] * inv;
            t2 += e8[k] * __ldg(a2hi + k);
        }
        e8[7] = t2 * LOG2E;
        *(uint4*)(g_e2h + (size_t)gid * 8) = pack8(e8);
    }
}

// ---------------- phase 2, layer 2 + fused log_softmax, unroll x2 ----------
__global__ void k_phase2_l2(float* __restrict__ H2out, float* __restrict__ logp)
{
    int gid = (blockIdx.x * blockDim.x + threadIdx.x) >> 3;
    if (gid >= N_NODES) return;
    const int ll = threadIdx.x & 7;
    int s = __ldg(g_noff + gid), e = __ldg(g_noff + gid + 1);
    float t1n = __ldg(g_t1 + gid);

    float acc[8];
#pragma unroll
    for (int k = 0; k < 8; k++) acc[k] = 0.f;
    float wsum = 0.f;

    int i = s + ll;
    for (; i + 8 < e; i += 16) {
        int ed0 = __ldg(g_pedge + i);
        int ed1 = __ldg(g_pedge + i + 8);
        uint4 v0 = *(const uint4*)(g_e2h + (size_t)ed0 * 8);
        uint4 v1 = *(const uint4*)(g_e2h + (size_t)ed1 * 8);
        float t20 = __half2float(((const __half*)&v0.w)[1]);
        float t21 = __half2float(((const __half*)&v1.w)[1]);
        float wv0 = exp2f(lrelu(t1n + t20));
        float wv1 = exp2f(lrelu(t1n + t21));
        wsum += wv0 + wv1;
        acc8(v0, acc, wv0);
        acc8(v1, acc, wv1);
    }
    if (i < e) {
        int ed = __ldg(g_pedge + i);
        uint4 v = *(const uint4*)(g_e2h + (size_t)ed * 8);
        float t2 = __half2float(((const __half*)&v.w)[1]);
        float wv = exp2f(lrelu(t1n + t2));
        wsum += wv;
        acc8(v, acc, wv);
    }
#pragma unroll
    for (int o = 4; o >= 1; o >>= 1) {
#pragma unroll
        for (int k = 0; k < 7; k++)
            acc[k] += __shfl_down_sync(FULLM, acc[k], o, 8);
        wsum += __shfl_down_sync(FULLM, wsum, o, 8);
    }

    if (ll == 0) {
        float inv = 1.f / (wsum + 1e-9f);
        float v[N_CLS];
        float m = -1e30f;
#pragma unroll
        for (int k = 0; k < N_CLS; k++) {
            v[k] = acc[k] * inv;
            m = fmaxf(m, v[k]);
        }
        float sx = 0.f;
#pragma unroll
        for (int k = 0; k < N_CLS; k++) sx += __expf(v[k] - m);
        float ls = m + __logf(sx);
        float* h2p = H2out + (size_t)gid * N_CLS;
        float* lpp = logp + (size_t)gid * N_CLS;
#pragma unroll
        for (int k = 0; k < N_CLS; k++) {
            h2p[k] = v[k];
            lpp[k] = v[k] - ls;
        }
    }
}

// ---------------- launch ---------------------------------------------------
// Enqueue order (4th kernel = ncu capture slot): zero(1,s1) eoff(2,main)
// count(3,s1) gemm1(4,main!) p1l1(5,main) scans+scatter(s1) join tail.
extern "C" void kernel_launch(void* const* d_in, const int* in_sizes, int n_in,
                              void* d_out, int out_size)
{
    const float* H   = (const float*)d_in[0];
    const float* W1  = (const float*)d_in[1];
    const float* a11 = (const float*)d_in[2];
    const float* a21 = (const float*)d_in[3];
    const float* W2  = (const float*)d_in[4];
    const float* a12 = (const float*)d_in[5];
    const float* a22 = (const float*)d_in[6];
    const int* node_idx = (const int*)d_in[7];
    const int* edge_idx = (const int*)d_in[8];

    float* out  = (float*)d_out;
    float* logp = out;                                              // [N, 7]
    float* H1   = out + (size_t)N_NODES * N_CLS;                    // [N, 16]
    float* H2   = out + (size_t)N_NODES * (N_CLS + D_HID);          // [N, 7]

    static cudaStream_t s1 = nullptr;
    static cudaEvent_t evF = nullptr, evJ = nullptr;
    if (s1 == nullptr) {
        cudaStreamCreateWithFlags(&s1, cudaStreamNonBlocking);
        cudaEventCreateWithFlags(&evF, cudaEventDisableTiming);
        cudaEventCreateWithFlags(&evJ, cudaEventDisableTiming);
    }

    // fork
    cudaEventRecord(evF, 0);
    cudaStreamWaitEvent(s1, evF, 0);

    // side: zero counts immediately (unblocks count early)
    k_zero<<<(N_NODES + 255) / 256, 256, 0, s1>>>();

    // main: edge offsets
    k_eoff<<<(N_EDGES + 255) / 256, 256>>>(edge_idx);

    // side: count
    k_count<<<(NNZ / 4 + 255) / 256, 256, 0, s1>>>((const int4*)node_idx);

    // main: tf32 tensor-core gemm1 (4th enqueued -> ncu capture)
    k_gemm1<<<(N_NODES + 127) / 128, 256>>>(H, W1, a11, a21);

    // main: phase1 L1
    k_phase1_l1<<<N_EDGES / 32, 256>>>(node_idx, a21 + D_HID);

    // side: rest of CSR build
    k_scan1<<<100, 1024, 0, s1>>>();
    k_scan2<<<1, 128, 0, s1>>>();
    k_scan3<<<100, 1024, 0, s1>>>();
    k_scatter<<<(NNZ / 4 + 255) / 256, 256, 0, s1>>>((const int4*)node_idx,
                                                     (const int4*)edge_idx);
    cudaEventRecord(evJ, s1);

    // join: node CSR needed from here on
    cudaStreamWaitEvent(0, evJ, 0);
    k_phase2_l1<<<N_NODES / 32, 256>>>(H1, W2, a12, a22);
    k_phase1_l2<<<N_EDGES / 32, 256>>>(node_idx, a22 + N_CLS);
    k_phase2_l2<<<N_NODES / 32, 256>>>(H2, logp);
}

// round 14
// speedup vs baseline: 1.1047x; 1.1047x over previous
#include <cuda_runtime.h>
#include <cuda_fp16.h>
#include <cstdint>
#include <cstddef>

#define N_NODES 100000
#define N_EDGES 100000
#define NNZ     3200000
#define D_IN    512
#define D_HID   16
#define N_CLS   7
#define LOG2E   1.4426950408889634f
#define FULLM   0xffffffffu

// ---------------- scratch (device globals) ---------------------------------
__device__ __align__(128) __half g_hu1h[(size_t)N_NODES * 16]; // L1 node rows: h*u fp16 (32B)
__device__ float  g_u1[N_NODES];                               // u fp32
__device__ __align__(128) __half g_e1h[(size_t)N_EDGES * 16];  // L1 edge rows: e fp16 (32B)
__device__ float  g_t2e1[N_EDGES];                             // (e.a2hi)*log2e fp32
__device__ __align__(128) __half g_hu2h[(size_t)N_NODES * 8];  // L2 node rows: [h2*u (7), u] (16B)
__device__ __align__(128) __half g_e2h[(size_t)N_EDGES * 8];   // L2 edge rows: [e2 (7), t2*log2e] (16B)
__device__ float  g_t1[N_NODES];                               // (h.a2lo)*log2e
__device__ int    g_eoff[N_EDGES + 1];
__device__ int    g_cnt[N_NODES];
__device__ int    g_noff[N_NODES + 1];
__device__ int    g_cur[N_NODES];
__device__ int    g_pedge[NNZ];
__device__ int    g_bsum[128];
__device__ int    g_bpre[128];

__device__ __forceinline__ float lrelu(float v) { return v > 0.f ? v : 0.2f * v; }

// ---- packed f32x2 helpers --------------------------------------------------
__device__ __forceinline__ unsigned long long splat2(float x) {
    unsigned long long r;
    unsigned int u = __float_as_uint(x);
    asm("mov.b64 %0, {%1, %1};" : "=l"(r) : "r"(u));
    return r;
}
__device__ __forceinline__ unsigned long long ffma2(unsigned long long a,
                                                    unsigned long long b,
                                                    unsigned long long c) {
    unsigned long long d;
    asm("fma.rn.f32x2 %0, %1, %2, %3;" : "=l"(d) : "l"(a), "l"(b), "l"(c));
    return d;
}
__device__ __forceinline__ void unpack2(unsigned long long v, float& lo, float& hi) {
    unsigned int a, b;
    asm("mov.b64 {%0, %1}, %2;" : "=r"(a), "=r"(b) : "l"(v));
    lo = __uint_as_float(a);
    hi = __uint_as_float(b);
}
__device__ __forceinline__ void acc8(const uint4& v, float* acc, float w) {
    float2 f0 = __half22float2(*(const __half2*)&v.x);
    float2 f1 = __half22float2(*(const __half2*)&v.y);
    float2 f2 = __half22float2(*(const __half2*)&v.z);
    float2 f3 = __half22float2(*(const __half2*)&v.w);
    acc[0] += w * f0.x; acc[1] += w * f0.y;
    acc[2] += w * f1.x; acc[3] += w * f1.y;
    acc[4] += w * f2.x; acc[5] += w * f2.y;
    acc[6] += w * f3.x; acc[7] += w * f3.y;
}
__device__ __forceinline__ void add8(const uint4& v, float* acc) {
    float2 f0 = __half22float2(*(const __half2*)&v.x);
    float2 f1 = __half22float2(*(const __half2*)&v.y);
    float2 f2 = __half22float2(*(const __half2*)&v.z);
    float2 f3 = __half22float2(*(const __half2*)&v.w);
    acc[0] += f0.x; acc[1] += f0.y;
    acc[2] += f1.x; acc[3] += f1.y;
    acc[4] += f2.x; acc[5] += f2.y;
    acc[6] += f3.x; acc[7] += f3.y;
}
__device__ __forceinline__ uint4 pack8(const float* e) {
    __half2 p[4];
    p[0] = __float22half2_rn(make_float2(e[0], e[1]));
    p[1] = __float22half2_rn(make_float2(e[2], e[3]));
    p[2] = __float22half2_rn(make_float2(e[4], e[5]));
    p[3] = __float22half2_rn(make_float2(e[6], e[7]));
    return *(uint4*)p;
}

// ---------------- k_zero ----------------------------------------------------
__global__ void k_zero()
{
    int n = blockIdx.x * blockDim.x + threadIdx.x;
    if (n < N_NODES) g_cnt[n] = 0;
}

// ---------------- edge offsets ---------------------------------------------
__global__ void k_eoff(const int* __restrict__ edge_idx)
{
    int e = blockIdx.x * blockDim.x + threadIdx.x;
    if (e >= N_EDGES) return;
    int lo = 0, hi = NNZ;
    while (lo < hi) {
        int m = (lo + hi) >> 1;
        if (__ldg(edge_idx + m) < e) lo = m + 1; else hi = m;
    }
    g_eoff[e] = lo;
    if (e == 0) g_eoff[N_EDGES] = NNZ;
}

// ---------------- node CSR build (8 elems/thread, 2 coalesced streams) -----
#define QUARTS (NNZ / 4)          // 800000 int4 elements
#define HALFQ  (QUARTS / 2)       // 400000
__global__ void k_count(const int4* __restrict__ node_idx4)
{
    int i = blockIdx.x * blockDim.x + threadIdx.x;
    if (i >= HALFQ) return;
    int4 a = __ldg(node_idx4 + i);
    int4 b = __ldg(node_idx4 + i + HALFQ);
    atomicAdd(&g_cnt[a.x], 1);
    atomicAdd(&g_cnt[b.x], 1);
    atomicAdd(&g_cnt[a.y], 1);
    atomicAdd(&g_cnt[b.y], 1);
    atomicAdd(&g_cnt[a.z], 1);
    atomicAdd(&g_cnt[b.z], 1);
    atomicAdd(&g_cnt[a.w], 1);
    atomicAdd(&g_cnt[b.w], 1);
}
__global__ void k_scan1()
{
    __shared__ int sp[1024];
    int t = threadIdx.x, b = blockIdx.x;
    int idx = b * 1000 + t;
    int v = (t < 1000) ? g_cnt[idx] : 0;
    sp[t] = v;
    __syncthreads();
    for (int o = 1; o < 1024; o <<= 1) {
        int u = (t >= o) ? sp[t - o] : 0;
        __syncthreads();
        sp[t] += u;
        __syncthreads();
    }
    if (t < 1000) g_noff[idx] = sp[t] - v;
    if (t == 1023) g_bsum[b] = sp[1023];
}
__global__ void k_scan2()
{
    __shared__ int sp[128];
    int t = threadIdx.x;
    int v = (t < 100) ? g_bsum[t] : 0;
    sp[t] = v;
    __syncthreads();
    for (int o = 1; o < 128; o <<= 1) {
        int u = (t >= o) ? sp[t - o] : 0;
        __syncthreads();
        sp[t] += u;
        __syncthreads();
    }
    if (t < 100) g_bpre[t] = sp[t] - v;
}
__global__ void k_scan3()
{
    int t = threadIdx.x, b = blockIdx.x;
    int idx = b * 1000 + t;
    if (t < 1000) {
        int o = g_noff[idx] + g_bpre[b];
        g_noff[idx] = o;
        g_cur[idx] = o;
    }
    if (idx == 0) g_noff[N_NODES] = NNZ;
}
__global__ void k_scatter(const int4* __restrict__ node_idx4, const int4* __restrict__ edge_idx4)
{
    int i = blockIdx.x * blockDim.x + threadIdx.x;
    if (i >= HALFQ) return;
    int4 na = __ldg(node_idx4 + i);
    int4 nb = __ldg(node_idx4 + i + HALFQ);
    int4 ea = __ldg(edge_idx4 + i);
    int4 eb = __ldg(edge_idx4 + i + HALFQ);
    int pa0 = atomicAdd(&g_cur[na.x], 1);
    int pb0 = atomicAdd(&g_cur[nb.x], 1);
    int pa1 = atomicAdd(&g_cur[na.y], 1);
    int pb1 = atomicAdd(&g_cur[nb.y], 1);
    g_pedge[pa0] = ea.x; g_pedge[pb0] = eb.x;
    g_pedge[pa1] = ea.y; g_pedge[pb1] = eb.y;
    int pa2 = atomicAdd(&g_cur[na.z], 1);
    int pb2 = atomicAdd(&g_cur[nb.z], 1);
    int pa3 = atomicAdd(&g_cur[na.w], 1);
    int pb3 = atomicAdd(&g_cur[nb.w], 1);
    g_pedge[pa2] = ea.z; g_pedge[pb2] = eb.z;
    g_pedge[pa3] = ea.w; g_pedge[pb3] = eb.w;
}

// ---------------- GEMM1 (FFMA2, DRAM-bound; proven ~30us) -------------------
__global__ void k_gemm1(const float* __restrict__ X, const float* __restrict__ W,
                        const float* __restrict__ a1, const float* __restrict__ a2lo)
{
    __shared__ __align__(16) float sX[128 * 65];
    __shared__ __align__(16) float sW[64 * 16];
    const int t = threadIdx.x;
    const int nbase = blockIdx.x * 128;
    const int ng = t >> 2, jg = t & 3;

    unsigned long long acc[4][2];
#pragma unroll
    for (int a = 0; a < 4; a++) { acc[a][0] = 0ull; acc[a][1] = 0ull; }

    for (int ck = 0; ck < D_IN; ck += 64) {
        for (int q = t; q < 128 * 16; q += 128) {
            int row = q >> 4, fc = q & 15;
            int n = nbase + row;
            float4 v = make_float4(0.f, 0.f, 0.f, 0.f);
            if (n < N_NODES) v = *(const float4*)(X + (size_t)n * D_IN + ck + fc * 4);
            int b = row * 65 + fc * 4;
            sX[b] = v.x; sX[b + 1] = v.y; sX[b + 2] = v.z; sX[b + 3] = v.w;
        }
        for (int q = t; q < 256; q += 128) {
            float4 v = *(const float4*)(W + ck * 16 + q * 4);
            *(float4*)(sW + q * 4) = v;
        }
        __syncthreads();
#pragma unroll 16
        for (int c = 0; c < 64; c++) {
            unsigned long long wp0 = *(const unsigned long long*)(sW + c * 16 + jg * 4);
            unsigned long long wp1 = *(const unsigned long long*)(sW + c * 16 + jg * 4 + 2);
#pragma unroll
            for (int a = 0; a < 4; a++) {
                unsigned long long xs = splat2(sX[(ng * 4 + a) * 65 + c]);
                acc[a][0] = ffma2(xs, wp0, acc[a][0]);
                acc[a][1] = ffma2(xs, wp1, acc[a][1]);
            }
        }
        __syncthreads();
    }

#pragma unroll
    for (int a = 0; a < 4; a++) {
        float v0, v1, v2, v3;
        unpack2(acc[a][0], v0, v1);
        unpack2(acc[a][1], v2, v3);
        int j = jg * 4;
        int srow = (ng * 4 + a) * 17;
        sX[srow + j] = v0; sX[srow + j + 1] = v1;
        sX[srow + j + 2] = v2; sX[srow + j + 3] = v3;
    }
    __syncthreads();
    {
        int n = nbase + t;
        if (n < N_NODES) {
            float hv[16];
            float uu = 0.f, tt = 0.f;
#pragma unroll
            for (int j = 0; j < D_HID; j++) {
                hv[j] = sX[t * 17 + j];
                uu += hv[j] * __ldg(a1 + j);
                tt += hv[j] * __ldg(a2lo + j);
            }
            float u = exp2f(lrelu(uu * LOG2E));
            float e0[8], e1[8];
#pragma unroll
            for (int j = 0; j < 8; j++) { e0[j] = hv[j] * u; e1[j] = hv[8 + j] * u; }
            __half* dst = g_hu1h + (size_t)n * 16;
            *(uint4*)dst = pack8(e0);
            *(uint4*)(dst + 8) = pack8(e1);
            g_u1[n] = u;
            g_t1[n] = tt * LOG2E;
        }
    }
}

// ---------------- phase 1, layer 1: 8-lane group per edge, unroll x4 -------
__global__ void k_phase1_l1(const int* __restrict__ node_idx, const float* __restrict__ a2hi)
{
    int gid = (blockIdx.x * blockDim.x + threadIdx.x) >> 3;
    if (gid >= N_EDGES) return;
    const int lane = threadIdx.x & 31;
    const int ll = lane & 7;
    const int r = ll & 1;
    int s = __ldg(g_eoff + gid), epos = __ldg(g_eoff + gid + 1);

    float acc[8];
#pragma unroll
    for (int k = 0; k < 8; k++) acc[k] = 0.f;
    float usum = 0.f;

    int i = s + (ll >> 1);
    for (; i + 12 < epos; i += 16) {
        int nd0 = __ldg(node_idx + i);
        int nd1 = __ldg(node_idx + i + 4);
        int nd2 = __ldg(node_idx + i + 8);
        int nd3 = __ldg(node_idx + i + 12);
        uint4 v0 = *((const uint4*)(g_hu1h + (size_t)nd0 * 16) + r);
        uint4 v1 = *((const uint4*)(g_hu1h + (size_t)nd1 * 16) + r);
        uint4 v2 = *((const uint4*)(g_hu1h + (size_t)nd2 * 16) + r);
        uint4 v3 = *((const uint4*)(g_hu1h + (size_t)nd3 * 16) + r);
        add8(v0, acc); add8(v1, acc); add8(v2, acc); add8(v3, acc);
        if (r == 0) usum += __ldg(g_u1 + nd0) + __ldg(g_u1 + nd1)
                          + __ldg(g_u1 + nd2) + __ldg(g_u1 + nd3);
    }
    for (; i < epos; i += 4) {
        int nd = __ldg(node_idx + i);
        uint4 v = *((const uint4*)(g_hu1h + (size_t)nd * 16) + r);
        add8(v, acc);
        if (r == 0) usum += __ldg(g_u1 + nd);
    }
#pragma unroll
    for (int o = 4; o >= 2; o >>= 1)
#pragma unroll
        for (int k = 0; k < 8; k++)
            acc[k] += __shfl_down_sync(FULLM, acc[k], o, 8);
    usum += __shfl_down_sync(FULLM, usum, 4, 8);
    usum += __shfl_down_sync(FULLM, usum, 2, 8);
    usum = __shfl_sync(FULLM, usum, 0, 8);
    float inv = 1.f / (usum + 1e-9f);

    float t2p = 0.f;
    if (ll < 2) {
        float e8[8];
#pragma unroll
        for (int k = 0; k < 8; k++) {
            e8[k] = acc[k] * inv;
            t2p += e8[k] * __ldg(a2hi + r * 8 + k);
        }
        *((uint4*)(g_e1h + (size_t)gid * 16) + r) = pack8(e8);
    }
    t2p += __shfl_xor_sync(FULLM, t2p, 1);
    if (ll == 0) g_t2e1[gid] = t2p * LOG2E;
}

// ---------------- phase 2, layer 1 + fused gemm2 epilogue, unroll x4 -------
__global__ void k_phase2_l1(float* __restrict__ H1out, const float* __restrict__ W2,
                            const float* __restrict__ a1, const float* __restrict__ a2lo)
{
    int gid = (blockIdx.x * blockDim.x + threadIdx.x) >> 3;
    if (gid >= N_NODES) return;
    const int lane = threadIdx.x & 31;
    const int ll = lane & 7;
    const int r = ll & 1;
    int s = __ldg(g_noff + gid), e = __ldg(g_noff + gid + 1);
    float t1n = __ldg(g_t1 + gid);

    float acc[8];
#pragma unroll
    for (int k = 0; k < 8; k++) acc[k] = 0.f;
    float wsum = 0.f;

    int i = s + (ll >> 1);
    for (; i + 12 < e; i += 16) {
        int ed0 = __ldg(g_pedge + i);
        int ed1 = __ldg(g_pedge + i + 4);
        int ed2 = __ldg(g_pedge + i + 8);
        int ed3 = __ldg(g_pedge + i + 12);
        float t20 = __ldg(g_t2e1 + ed0);
        float t21 = __ldg(g_t2e1 + ed1);
        float t22 = __ldg(g_t2e1 + ed2);
        float t23 = __ldg(g_t2e1 + ed3);
        uint4 v0 = *((const uint4*)(g_e1h + (size_t)ed0 * 16) + r);
        uint4 v1 = *((const uint4*)(g_e1h + (size_t)ed1 * 16) + r);
        uint4 v2 = *((const uint4*)(g_e1h + (size_t)ed2 * 16) + r);
        uint4 v3 = *((const uint4*)(g_e1h + (size_t)ed3 * 16) + r);
        float wv0 = exp2f(lrelu(t1n + t20));
        float wv1 = exp2f(lrelu(t1n + t21));
        float wv2 = exp2f(lrelu(t1n + t22));
        float wv3 = exp2f(lrelu(t1n + t23));
        if (r == 1) wsum += (wv0 + wv1) + (wv2 + wv3);
        acc8(v0, acc, wv0); acc8(v1, acc, wv1);
        acc8(v2, acc, wv2); acc8(v3, acc, wv3);
    }
    for (; i < e; i += 4) {
        int ed = __ldg(g_pedge + i);
        float wv = exp2f(lrelu(t1n + __ldg(g_t2e1 + ed)));
        if (r == 1) wsum += wv;
        uint4 v = *((const uint4*)(g_e1h + (size_t)ed * 16) + r);
        acc8(v, acc, wv);
    }
#pragma unroll
    for (int o = 4; o >= 2; o >>= 1)
#pragma unroll
        for (int k = 0; k < 8; k++)
            acc[k] += __shfl_down_sync(FULLM, acc[k], o, 8);
    wsum += __shfl_down_sync(FULLM, wsum, 4, 8);
    wsum += __shfl_down_sync(FULLM, wsum, 2, 8);
    wsum = __shfl_sync(FULLM, wsum, 1, 8);
    float inv = 1.f / (wsum + 1e-9f);

    float hk[8];
#pragma unroll
    for (int k = 0; k < 8; k++) hk[k] = acc[k] * inv;
    if (ll < 2) {
        *(float4*)(H1out + (size_t)gid * 16 + r * 8) =
            make_float4(hk[0], hk[1], hk[2], hk[3]);
        *(float4*)(H1out + (size_t)gid * 16 + r * 8 + 4) =
            make_float4(hk[4], hk[5], hk[6], hk[7]);
    }

    float h1a = 0.f, h1b = 0.f;
#pragma unroll
    for (int k = 0; k < 8; k++) {
        float t0 = __shfl_sync(FULLM, hk[k], 0, 8);
        float t1v = __shfl_sync(FULLM, hk[k], 1, 8);
        if (ll == k) { h1a = t0; h1b = t1v; }
    }
    float xa = h1a > 0.f ? h1a : expm1f(h1a);
    float xb = h1b > 0.f ? h1b : expm1f(h1b);
    float sarr[N_CLS];
#pragma unroll
    for (int jj = 0; jj < N_CLS; jj++) {
        float p = xa * __ldg(W2 + ll * N_CLS + jj) + xb * __ldg(W2 + (ll + 8) * N_CLS + jj);
        p += __shfl_down_sync(FULLM, p, 4, 8);
        p += __shfl_down_sync(FULLM, p, 2, 8);
        p += __shfl_down_sync(FULLM, p, 1, 8);
        sarr[jj] = p;
    }
    if (ll == 0) {
        float uu = 0.f, tt = 0.f;
#pragma unroll
        for (int jj = 0; jj < N_CLS; jj++) {
            uu += sarr[jj] * __ldg(a1 + jj);
            tt += sarr[jj] * __ldg(a2lo + jj);
        }
        float u = exp2f(lrelu(uu * LOG2E));
        float e8[8];
#pragma unroll
        for (int jj = 0; jj < N_CLS; jj++) e8[jj] = sarr[jj] * u;
        e8[7] = u;
        *(uint4*)(g_hu2h + (size_t)gid * 8) = pack8(e8);
        g_t1[gid] = tt * LOG2E;
    }
}

// ---------------- phase 1, layer 2: unroll x2 ------------------------------
__global__ void k_phase1_l2(const int* __restrict__ node_idx, const float* __restrict__ a2hi)
{
    int gid = (blockIdx.x * blockDim.x + threadIdx.x) >> 3;
    if (gid >= N_EDGES) return;
    const int ll = threadIdx.x & 7;
    int s = __ldg(g_eoff + gid), epos = __ldg(g_eoff + gid + 1);

    float acc[8];
#pragma unroll
    for (int k = 0; k < 8; k++) acc[k] = 0.f;

    int i = s + ll;
    for (; i + 8 < epos; i += 16) {
        int nd0 = __ldg(node_idx + i);
        int nd1 = __ldg(node_idx + i + 8);
        uint4 v0 = *(const uint4*)(g_hu2h + (size_t)nd0 * 8);
        uint4 v1 = *(const uint4*)(g_hu2h + (size_t)nd1 * 8);
        add8(v0, acc);
        add8(v1, acc);
    }
    if (i < epos) {
        int nd = __ldg(node_idx + i);
        uint4 v = *(const uint4*)(g_hu2h + (size_t)nd * 8);
        add8(v, acc);
    }
#pragma unroll
    for (int o = 4; o >= 1; o >>= 1)
#pragma unroll
        for (int k = 0; k < 8; k++)
            acc[k] += __shfl_down_sync(FULLM, acc[k], o, 8);

    if (ll == 0) {
        float inv = 1.f / (acc[7] + 1e-9f);
        float e8[8];
        float t2 = 0.f;
#pragma unroll
        for (int k = 0; k < 7; k++) {
            e8[k] = acc[k] * inv;
            t2 += e8[k] * __ldg(a2hi + k);
        }
        e8[7] = t2 * LOG2E;
        *(uint4*)(g_e2h + (size_t)gid * 8) = pack8(e8);
    }
}

// ---------------- phase 2, layer 2 + fused log_softmax, unroll x2 ----------
__global__ void k_phase2_l2(float* __restrict__ H2out, float* __restrict__ logp)
{
    int gid = (blockIdx.x * blockDim.x + threadIdx.x) >> 3;
    if (gid >= N_NODES) return;
    const int ll = threadIdx.x & 7;
    int s = __ldg(g_noff + gid), e = __ldg(g_noff + gid + 1);
    float t1n = __ldg(g_t1 + gid);

    float acc[8];
#pragma unroll
    for (int k = 0; k < 8; k++) acc[k] = 0.f;
    float wsum = 0.f;

    int i = s + ll;
    for (; i + 8 < e; i += 16) {
        int ed0 = __ldg(g_pedge + i);
        int ed1 = __ldg(g_pedge + i + 8);
        uint4 v0 = *(const uint4*)(g_e2h + (size_t)ed0 * 8);
        uint4 v1 = *(const uint4*)(g_e2h + (size_t)ed1 * 8);
        float t20 = __half2float(((const __half*)&v0.w)[1]);
        float t21 = __half2float(((const __half*)&v1.w)[1]);
        float wv0 = exp2f(lrelu(t1n + t20));
        float wv1 = exp2f(lrelu(t1n + t21));
        wsum += wv0 + wv1;
        acc8(v0, acc, wv0);
        acc8(v1, acc, wv1);
    }
    if (i < e) {
        int ed = __ldg(g_pedge + i);
        uint4 v = *(const uint4*)(g_e2h + (size_t)ed * 8);
        float t2 = __half2float(((const __half*)&v.w)[1]);
        float wv = exp2f(lrelu(t1n + t2));
        wsum += wv;
        acc8(v, acc, wv);
    }
#pragma unroll
    for (int o = 4; o >= 1; o >>= 1) {
#pragma unroll
        for (int k = 0; k < 7; k++)
            acc[k] += __shfl_down_sync(FULLM, acc[k], o, 8);
        wsum += __shfl_down_sync(FULLM, wsum, o, 8);
    }

    if (ll == 0) {
        float inv = 1.f / (wsum + 1e-9f);
        float v[N_CLS];
        float m = -1e30f;
#pragma unroll
        for (int k = 0; k < N_CLS; k++) {
            v[k] = acc[k] * inv;
            m = fmaxf(m, v[k]);
        }
        float sx = 0.f;
#pragma unroll
        for (int k = 0; k < N_CLS; k++) sx += __expf(v[k] - m);
        float ls = m + __logf(sx);
        float* h2p = H2out + (size_t)gid * N_CLS;
        float* lpp = logp + (size_t)gid * N_CLS;
#pragma unroll
        for (int k = 0; k < N_CLS; k++) {
            h2p[k] = v[k];
            lpp[k] = v[k] - ls;
        }
    }
}

// ---------------- launch ---------------------------------------------------
// Enqueue: zero(1,s1) eoff(2,main) count(3,s1) gemm1(4,main=capture slot)
// p1l1(5,main) scans+scatter(s1) join tail.
extern "C" void kernel_launch(void* const* d_in, const int* in_sizes, int n_in,
                              void* d_out, int out_size)
{
    const float* H   = (const float*)d_in[0];
    const float* W1  = (const float*)d_in[1];
    const float* a11 = (const float*)d_in[2];
    const float* a21 = (const float*)d_in[3];
    const float* W2  = (const float*)d_in[4];
    const float* a12 = (const float*)d_in[5];
    const float* a22 = (const float*)d_in[6];
    const int* node_idx = (const int*)d_in[7];
    const int* edge_idx = (const int*)d_in[8];

    float* out  = (float*)d_out;
    float* logp = out;                                              // [N, 7]
    float* H1   = out + (size_t)N_NODES * N_CLS;                    // [N, 16]
    float* H2   = out + (size_t)N_NODES * (N_CLS + D_HID);          // [N, 7]

    static cudaStream_t s1 = nullptr;
    static cudaEvent_t evF = nullptr, evJ = nullptr;
    if (s1 == nullptr) {
        cudaStreamCreateWithFlags(&s1, cudaStreamNonBlocking);
        cudaEventCreateWithFlags(&evF, cudaEventDisableTiming);
        cudaEventCreateWithFlags(&evJ, cudaEventDisableTiming);
    }

    // fork
    cudaEventRecord(evF, 0);
    cudaStreamWaitEvent(s1, evF, 0);

    // side: zero counts
    k_zero<<<(N_NODES + 255) / 256, 256, 0, s1>>>();

    // main: edge offsets
    k_eoff<<<(N_EDGES + 255) / 256, 256>>>(edge_idx);

    // side: count (8 elems/thread)
    k_count<<<(HALFQ + 255) / 256, 256, 0, s1>>>((const int4*)node_idx);

    // main: FFMA2 gemm1 (4th enqueued -> ncu capture)
    k_gemm1<<<(N_NODES + 127) / 128, 128>>>(H, W1, a11, a21);

    // main: phase1 L1
    k_phase1_l1<<<N_EDGES / 32, 256>>>(node_idx, a21 + D_HID);

    // side: rest of CSR build
    k_scan1<<<100, 1024, 0, s1>>>();
    k_scan2<<<1, 128, 0, s1>>>();
    k_scan3<<<100, 1024, 0, s1>>>();
    k_scatter<<<(HALFQ + 255) / 256, 256, 0, s1>>>((const int4*)node_idx,
                                                   (const int4*)edge_idx);
    cudaEventRecord(evJ, s1);

    // join: node CSR needed from here on
    cudaStreamWaitEvent(0, evJ, 0);
    k_phase2_l1<<<N_NODES / 32, 256>>>(H1, W2, a12, a22);
    k_phase1_l2<<<N_EDGES / 32, 256>>>(node_idx, a22 + N_CLS);
    k_phase2_l2<<<N_NODES / 32, 256>>>(H2, logp);
}

// round 15
// speedup vs baseline: 1.3253x; 1.1997x over previous
#include <cuda_runtime.h>
#include <cuda_fp16.h>
#include <cstdint>
#include <cstddef>

#define N_NODES 100000
#define N_EDGES 100000
#define NNZ     3200000
#define D_IN    512
#define D_HID   16
#define N_CLS   7
#define LOG2E   1.4426950408889634f
#define FULLM   0xffffffffu

// ---------------- scratch (device globals) ---------------------------------
__device__ __align__(128) __half g_hu1h[(size_t)N_NODES * 16]; // L1 node rows: h*u fp16 (32B)
__device__ float  g_u1[N_NODES];                               // u fp32
__device__ __align__(128) __half g_e1h[(size_t)N_EDGES * 16];  // L1 edge rows: e fp16 (32B)
__device__ float  g_t2e1[N_EDGES];                             // (e.a2hi)*log2e fp32
__device__ __align__(128) __half g_hu2h[(size_t)N_NODES * 8];  // L2 node rows: [h2*u (7), u] (16B)
__device__ __align__(128) __half g_e2h[(size_t)N_EDGES * 8];   // L2 edge rows: [e2 (7), t2*log2e] (16B)
__device__ float  g_t1[N_NODES];                               // (h.a2lo)*log2e
__device__ int    g_eoff[N_EDGES + 1];
__device__ int    g_cnt[N_NODES];
__device__ int    g_noff[N_NODES + 1];
__device__ int    g_cur[N_NODES];
__device__ int    g_pedge[NNZ];
__device__ int    g_bsum[128];
__device__ int    g_bpre[128];

__device__ __forceinline__ float lrelu(float v) { return v > 0.f ? v : 0.2f * v; }

// ---- packed f32x2 helpers --------------------------------------------------
__device__ __forceinline__ unsigned long long splat2(float x) {
    unsigned long long r;
    unsigned int u = __float_as_uint(x);
    asm("mov.b64 %0, {%1, %1};" : "=l"(r) : "r"(u));
    return r;
}
__device__ __forceinline__ unsigned long long ffma2(unsigned long long a,
                                                    unsigned long long b,
                                                    unsigned long long c) {
    unsigned long long d;
    asm("fma.rn.f32x2 %0, %1, %2, %3;" : "=l"(d) : "l"(a), "l"(b), "l"(c));
    return d;
}
__device__ __forceinline__ void unpack2(unsigned long long v, float& lo, float& hi) {
    unsigned int a, b;
    asm("mov.b64 {%0, %1}, %2;" : "=r"(a), "=r"(b) : "l"(v));
    lo = __uint_as_float(a);
    hi = __uint_as_float(b);
}
__device__ __forceinline__ void acc8(const uint4& v, float* acc, float w) {
    float2 f0 = __half22float2(*(const __half2*)&v.x);
    float2 f1 = __half22float2(*(const __half2*)&v.y);
    float2 f2 = __half22float2(*(const __half2*)&v.z);
    float2 f3 = __half22float2(*(const __half2*)&v.w);
    acc[0] += w * f0.x; acc[1] += w * f0.y;
    acc[2] += w * f1.x; acc[3] += w * f1.y;
    acc[4] += w * f2.x; acc[5] += w * f2.y;
    acc[6] += w * f3.x; acc[7] += w * f3.y;
}
__device__ __forceinline__ void add8(const uint4& v, float* acc) {
    float2 f0 = __half22float2(*(const __half2*)&v.x);
    float2 f1 = __half22float2(*(const __half2*)&v.y);
    float2 f2 = __half22float2(*(const __half2*)&v.z);
    float2 f3 = __half22float2(*(const __half2*)&v.w);
    acc[0] += f0.x; acc[1] += f0.y;
    acc[2] += f1.x; acc[3] += f1.y;
    acc[4] += f2.x; acc[5] += f2.y;
    acc[6] += f3.x; acc[7] += f3.y;
}
__device__ __forceinline__ uint4 pack8(const float* e) {
    __half2 p[4];
    p[0] = __float22half2_rn(make_float2(e[0], e[1]));
    p[1] = __float22half2_rn(make_float2(e[2], e[3]));
    p[2] = __float22half2_rn(make_float2(e[4], e[5]));
    p[3] = __float22half2_rn(make_float2(e[6], e[7]));
    return *(uint4*)p;
}

// ---------------- k_zero ----------------------------------------------------
__global__ void k_zero()
{
    int n = blockIdx.x * blockDim.x + threadIdx.x;
    if (n < N_NODES) g_cnt[n] = 0;
}

// ---------------- edge offsets ---------------------------------------------
__global__ void k_eoff(const int* __restrict__ edge_idx)
{
    int e = blockIdx.x * blockDim.x + threadIdx.x;
    if (e >= N_EDGES) return;
    int lo = 0, hi = NNZ;
    while (lo < hi) {
        int m = (lo + hi) >> 1;
        if (__ldg(edge_idx + m) < e) lo = m + 1; else hi = m;
    }
    g_eoff[e] = lo;
    if (e == 0) g_eoff[N_EDGES] = NNZ;
}

// ---------------- node CSR build (plain 4-wide; R11-measured best) ---------
__global__ void k_count(const int4* __restrict__ node_idx4)
{
    int i = blockIdx.x * blockDim.x + threadIdx.x;
    if (i >= NNZ / 4) return;
    int4 v = node_idx4[i];
    atomicAdd(&g_cnt[v.x], 1);
    atomicAdd(&g_cnt[v.y], 1);
    atomicAdd(&g_cnt[v.z], 1);
    atomicAdd(&g_cnt[v.w], 1);
}
__global__ void k_scan1()
{
    __shared__ int sp[1024];
    int t = threadIdx.x, b = blockIdx.x;
    int idx = b * 1000 + t;
    int v = (t < 1000) ? g_cnt[idx] : 0;
    sp[t] = v;
    __syncthreads();
    for (int o = 1; o < 1024; o <<= 1) {
        int u = (t >= o) ? sp[t - o] : 0;
        __syncthreads();
        sp[t] += u;
        __syncthreads();
    }
    if (t < 1000) g_noff[idx] = sp[t] - v;
    if (t == 1023) g_bsum[b] = sp[1023];
}
__global__ void k_scan2()
{
    __shared__ int sp[128];
    int t = threadIdx.x;
    int v = (t < 100) ? g_bsum[t] : 0;
    sp[t] = v;
    __syncthreads();
    for (int o = 1; o < 128; o <<= 1) {
        int u = (t >= o) ? sp[t - o] : 0;
        __syncthreads();
        sp[t] += u;
        __syncthreads();
    }
    if (t < 100) g_bpre[t] = sp[t] - v;
}
__global__ void k_scan3()
{
    int t = threadIdx.x, b = blockIdx.x;
    int idx = b * 1000 + t;
    if (t < 1000) {
        int o = g_noff[idx] + g_bpre[b];
        g_noff[idx] = o;
        g_cur[idx] = o;
    }
    if (idx == 0) g_noff[N_NODES] = NNZ;
}
__global__ void k_scatter(const int4* __restrict__ node_idx4, const int4* __restrict__ edge_idx4)
{
    int i = blockIdx.x * blockDim.x + threadIdx.x;
    if (i >= NNZ / 4) return;
    int4 nd = node_idx4[i];
    int4 ed = edge_idx4[i];
    g_pedge[atomicAdd(&g_cur[nd.x], 1)] = ed.x;
    g_pedge[atomicAdd(&g_cur[nd.y], 1)] = ed.y;
    g_pedge[atomicAdd(&g_cur[nd.z], 1)] = ed.z;
    g_pedge[atomicAdd(&g_cur[nd.w], 1)] = ed.w;
}

// ---------------- GEMM1 (FFMA2, 32-col chunks -> 19KB smem, occ 75%) -------
__global__ void k_gemm1(const float* __restrict__ X, const float* __restrict__ W,
                        const float* __restrict__ a1, const float* __restrict__ a2lo)
{
    __shared__ __align__(16) float sX[128 * 33];   // 16.9KB; reused as D stage (stride 17)
    __shared__ __align__(16) float sW[32 * 16];    // 2KB
    const int t = threadIdx.x;
    const int nbase = blockIdx.x * 128;
    const int ng = t >> 2, jg = t & 3;

    unsigned long long acc[4][2];
#pragma unroll
    for (int a = 0; a < 4; a++) { acc[a][0] = 0ull; acc[a][1] = 0ull; }

    for (int ck = 0; ck < D_IN; ck += 32) {
        // load X chunk: 128 rows x 32 cols (8 float4 per thread, coalesced)
#pragma unroll
        for (int it = 0; it < 8; it++) {
            int q = t + it * 128;
            int row = q >> 3, fc = q & 7;
            int n = nbase + row;
            float4 v = make_float4(0.f, 0.f, 0.f, 0.f);
            if (n < N_NODES) v = *(const float4*)(X + (size_t)n * D_IN + ck + fc * 4);
            int b = row * 33 + fc * 4;
            sX[b] = v.x; sX[b + 1] = v.y; sX[b + 2] = v.z; sX[b + 3] = v.w;
        }
        // load W chunk: 32 x 16 (1 float4 per thread)
        {
            float4 v = *(const float4*)(W + ck * 16 + t * 4);
            *(float4*)(sW + t * 4) = v;
        }
        __syncthreads();
#pragma unroll
        for (int c = 0; c < 32; c++) {
            unsigned long long wp0 = *(const unsigned long long*)(sW + c * 16 + jg * 4);
            unsigned long long wp1 = *(const unsigned long long*)(sW + c * 16 + jg * 4 + 2);
#pragma unroll
            for (int a = 0; a < 4; a++) {
                unsigned long long xs = splat2(sX[(ng * 4 + a) * 33 + c]);
                acc[a][0] = ffma2(xs, wp0, acc[a][0]);
                acc[a][1] = ffma2(xs, wp1, acc[a][1]);
            }
        }
        __syncthreads();
    }

#pragma unroll
    for (int a = 0; a < 4; a++) {
        float v0, v1, v2, v3;
        unpack2(acc[a][0], v0, v1);
        unpack2(acc[a][1], v2, v3);
        int j = jg * 4;
        int srow = (ng * 4 + a) * 17;
        sX[srow + j] = v0; sX[srow + j + 1] = v1;
        sX[srow + j + 2] = v2; sX[srow + j + 3] = v3;
    }
    __syncthreads();
    {
        int n = nbase + t;
        if (n < N_NODES) {
            float hv[16];
            float uu = 0.f, tt = 0.f;
#pragma unroll
            for (int j = 0; j < D_HID; j++) {
                hv[j] = sX[t * 17 + j];
                uu += hv[j] * __ldg(a1 + j);
                tt += hv[j] * __ldg(a2lo + j);
            }
            float u = exp2f(lrelu(uu * LOG2E));
            float e0[8], e1[8];
#pragma unroll
            for (int j = 0; j < 8; j++) { e0[j] = hv[j] * u; e1[j] = hv[8 + j] * u; }
            __half* dst = g_hu1h + (size_t)n * 16;
            *(uint4*)dst = pack8(e0);
            *(uint4*)(dst + 8) = pack8(e1);
            g_u1[n] = u;
            g_t1[n] = tt * LOG2E;
        }
    }
}

// ---------------- phase 1, layer 1: 8-lane group per edge, unroll x4 -------
__global__ void k_phase1_l1(const int* __restrict__ node_idx, const float* __restrict__ a2hi)
{
    int gid = (blockIdx.x * blockDim.x + threadIdx.x) >> 3;
    if (gid >= N_EDGES) return;
    const int lane = threadIdx.x & 31;
    const int ll = lane & 7;
    const int r = ll & 1;
    int s = __ldg(g_eoff + gid), epos = __ldg(g_eoff + gid + 1);

    float acc[8];
#pragma unroll
    for (int k = 0; k < 8; k++) acc[k] = 0.f;
    float usum = 0.f;

    int i = s + (ll >> 1);
    for (; i + 12 < epos; i += 16) {
        int nd0 = __ldg(node_idx + i);
        int nd1 = __ldg(node_idx + i + 4);
        int nd2 = __ldg(node_idx + i + 8);
        int nd3 = __ldg(node_idx + i + 12);
        uint4 v0 = *((const uint4*)(g_hu1h + (size_t)nd0 * 16) + r);
        uint4 v1 = *((const uint4*)(g_hu1h + (size_t)nd1 * 16) + r);
        uint4 v2 = *((const uint4*)(g_hu1h + (size_t)nd2 * 16) + r);
        uint4 v3 = *((const uint4*)(g_hu1h + (size_t)nd3 * 16) + r);
        add8(v0, acc); add8(v1, acc); add8(v2, acc); add8(v3, acc);
        if (r == 0) usum += __ldg(g_u1 + nd0) + __ldg(g_u1 + nd1)
                          + __ldg(g_u1 + nd2) + __ldg(g_u1 + nd3);
    }
    for (; i < epos; i += 4) {
        int nd = __ldg(node_idx + i);
        uint4 v = *((const uint4*)(g_hu1h + (size_t)nd * 16) + r);
        add8(v, acc);
        if (r == 0) usum += __ldg(g_u1 + nd);
    }
#pragma unroll
    for (int o = 4; o >= 2; o >>= 1)
#pragma unroll
        for (int k = 0; k < 8; k++)
            acc[k] += __shfl_down_sync(FULLM, acc[k], o, 8);
    usum += __shfl_down_sync(FULLM, usum, 4, 8);
    usum += __shfl_down_sync(FULLM, usum, 2, 8);
    usum = __shfl_sync(FULLM, usum, 0, 8);
    float inv = 1.f / (usum + 1e-9f);

    float t2p = 0.f;
    if (ll < 2) {
        float e8[8];
#pragma unroll
        for (int k = 0; k < 8; k++) {
            e8[k] = acc[k] * inv;
            t2p += e8[k] * __ldg(a2hi + r * 8 + k);
        }
        *((uint4*)(g_e1h + (size_t)gid * 16) + r) = pack8(e8);
    }
    t2p += __shfl_xor_sync(FULLM, t2p, 1);
    if (ll == 0) g_t2e1[gid] = t2p * LOG2E;
}

// ---------------- phase 2, layer 1 + fused gemm2 epilogue, unroll x4 -------
__global__ void k_phase2_l1(float* __restrict__ H1out, const float* __restrict__ W2,
                            const float* __restrict__ a1, const float* __restrict__ a2lo)
{
    int gid = (blockIdx.x * blockDim.x + threadIdx.x) >> 3;
    if (gid >= N_NODES) return;
    const int lane = threadIdx.x & 31;
    const int ll = lane & 7;
    const int r = ll & 1;
    int s = __ldg(g_noff + gid), e = __ldg(g_noff + gid + 1);
    float t1n = __ldg(g_t1 + gid);

    float acc[8];
#pragma unroll
    for (int k = 0; k < 8; k++) acc[k] = 0.f;
    float wsum = 0.f;

    int i = s + (ll >> 1);
    for (; i + 12 < e; i += 16) {
        int ed0 = __ldg(g_pedge + i);
        int ed1 = __ldg(g_pedge + i + 4);
        int ed2 = __ldg(g_pedge + i + 8);
        int ed3 = __ldg(g_pedge + i + 12);
        float t20 = __ldg(g_t2e1 + ed0);
        float t21 = __ldg(g_t2e1 + ed1);
        float t22 = __ldg(g_t2e1 + ed2);
        float t23 = __ldg(g_t2e1 + ed3);
        uint4 v0 = *((const uint4*)(g_e1h + (size_t)ed0 * 16) + r);
        uint4 v1 = *((const uint4*)(g_e1h + (size_t)ed1 * 16) + r);
        uint4 v2 = *((const uint4*)(g_e1h + (size_t)ed2 * 16) + r);
        uint4 v3 = *((const uint4*)(g_e1h + (size_t)ed3 * 16) + r);
        float wv0 = exp2f(lrelu(t1n + t20));
        float wv1 = exp2f(lrelu(t1n + t21));
        float wv2 = exp2f(lrelu(t1n + t22));
        float wv3 = exp2f(lrelu(t1n + t23));
        if (r == 1) wsum += (wv0 + wv1) + (wv2 + wv3);
        acc8(v0, acc, wv0); acc8(v1, acc, wv1);
        acc8(v2, acc, wv2); acc8(v3, acc, wv3);
    }
    for (; i < e; i += 4) {
        int ed = __ldg(g_pedge + i);
        float wv = exp2f(lrelu(t1n + __ldg(g_t2e1 + ed)));
        if (r == 1) wsum += wv;
        uint4 v = *((const uint4*)(g_e1h + (size_t)ed * 16) + r);
        acc8(v, acc, wv);
    }
#pragma unroll
    for (int o = 4; o >= 2; o >>= 1)
#pragma unroll
        for (int k = 0; k < 8; k++)
            acc[k] += __shfl_down_sync(FULLM, acc[k], o, 8);
    wsum += __shfl_down_sync(FULLM, wsum, 4, 8);
    wsum += __shfl_down_sync(FULLM, wsum, 2, 8);
    wsum = __shfl_sync(FULLM, wsum, 1, 8);
    float inv = 1.f / (wsum + 1e-9f);

    float hk[8];
#pragma unroll
    for (int k = 0; k < 8; k++) hk[k] = acc[k] * inv;
    if (ll < 2) {
        *(float4*)(H1out + (size_t)gid * 16 + r * 8) =
            make_float4(hk[0], hk[1], hk[2], hk[3]);
        *(float4*)(H1out + (size_t)gid * 16 + r * 8 + 4) =
            make_float4(hk[4], hk[5], hk[6], hk[7]);
    }

    float h1a = 0.f, h1b = 0.f;
#pragma unroll
    for (int k = 0; k < 8; k++) {
        float t0 = __shfl_sync(FULLM, hk[k], 0, 8);
        float t1v = __shfl_sync(FULLM, hk[k], 1, 8);
        if (ll == k) { h1a = t0; h1b = t1v; }
    }
    float xa = h1a > 0.f ? h1a : expm1f(h1a);
    float xb = h1b > 0.f ? h1b : expm1f(h1b);
    float sarr[N_CLS];
#pragma unroll
    for (int jj = 0; jj < N_CLS; jj++) {
        float p = xa * __ldg(W2 + ll * N_CLS + jj) + xb * __ldg(W2 + (ll + 8) * N_CLS + jj);
        p += __shfl_down_sync(FULLM, p, 4, 8);
        p += __shfl_down_sync(FULLM, p, 2, 8);
        p += __shfl_down_sync(FULLM, p, 1, 8);
        sarr[jj] = p;
    }
    if (ll == 0) {
        float uu = 0.f, tt = 0.f;
#pragma unroll
        for (int jj = 0; jj < N_CLS; jj++) {
            uu += sarr[jj] * __ldg(a1 + jj);
            tt += sarr[jj] * __ldg(a2lo + jj);
        }
        float u = exp2f(lrelu(uu * LOG2E));
        float e8[8];
#pragma unroll
        for (int jj = 0; jj < N_CLS; jj++) e8[jj] = sarr[jj] * u;
        e8[7] = u;
        *(uint4*)(g_hu2h + (size_t)gid * 8) = pack8(e8);
        g_t1[gid] = tt * LOG2E;
    }
}

// ---------------- phase 1, layer 2: unroll x2 ------------------------------
__global__ void k_phase1_l2(const int* __restrict__ node_idx, const float* __restrict__ a2hi)
{
    int gid = (blockIdx.x * blockDim.x + threadIdx.x) >> 3;
    if (gid >= N_EDGES) return;
    const int ll = threadIdx.x & 7;
    int s = __ldg(g_eoff + gid), epos = __ldg(g_eoff + gid + 1);

    float acc[8];
#pragma unroll
    for (int k = 0; k < 8; k++) acc[k] = 0.f;

    int i = s + ll;
    for (; i + 8 < epos; i += 16) {
        int nd0 = __ldg(node_idx + i);
        int nd1 = __ldg(node_idx + i + 8);
        uint4 v0 = *(const uint4*)(g_hu2h + (size_t)nd0 * 8);
        uint4 v1 = *(const uint4*)(g_hu2h + (size_t)nd1 * 8);
        add8(v0, acc);
        add8(v1, acc);
    }
    if (i < epos) {
        int nd = __ldg(node_idx + i);
        uint4 v = *(const uint4*)(g_hu2h + (size_t)nd * 8);
        add8(v, acc);
    }
#pragma unroll
    for (int o = 4; o >= 1; o >>= 1)
#pragma unroll
        for (int k = 0; k < 8; k++)
            acc[k] += __shfl_down_sync(FULLM, acc[k], o, 8);

    if (ll == 0) {
        float inv = 1.f / (acc[7] + 1e-9f);
        float e8[8];
        float t2 = 0.f;
#pragma unroll
        for (int k = 0; k < 7; k++) {
            e8[k] = acc[k] * inv;
            t2 += e8[k] * __ldg(a2hi + k);
        }
        e8[7] = t2 * LOG2E;
        *(uint4*)(g_e2h + (size_t)gid * 8) = pack8(e8);
    }
}

// ---------------- phase 2, layer 2 + fused log_softmax, unroll x2 ----------
__global__ void k_phase2_l2(float* __restrict__ H2out, float* __restrict__ logp)
{
    int gid = (blockIdx.x * blockDim.x + threadIdx.x) >> 3;
    if (gid >= N_NODES) return;
    const int ll = threadIdx.x & 7;
    int s = __ldg(g_noff + gid), e = __ldg(g_noff + gid + 1);
    float t1n = __ldg(g_t1 + gid);

    float acc[8];
#pragma unroll
    for (int k = 0; k < 8; k++) acc[k] = 0.f;
    float wsum = 0.f;

    int i = s + ll;
    for (; i + 8 < e; i += 16) {
        int ed0 = __ldg(g_pedge + i);
        int ed1 = __ldg(g_pedge + i + 8);
        uint4 v0 = *(const uint4*)(g_e2h + (size_t)ed0 * 8);
        uint4 v1 = *(const uint4*)(g_e2h + (size_t)ed1 * 8);
        float t20 = __half2float(((const __half*)&v0.w)[1]);
        float t21 = __half2float(((const __half*)&v1.w)[1]);
        float wv0 = exp2f(lrelu(t1n + t20));
        float wv1 = exp2f(lrelu(t1n + t21));
        wsum += wv0 + wv1;
        acc8(v0, acc, wv0);
        acc8(v1, acc, wv1);
    }
    if (i < e) {
        int ed = __ldg(g_pedge + i);
        uint4 v = *(const uint4*)(g_e2h + (size_t)ed * 8);
        float t2 = __half2float(((const __half*)&v.w)[1]);
        float wv = exp2f(lrelu(t1n + t2));
        wsum += wv;
        acc8(v, acc, wv);
    }
#pragma unroll
    for (int o = 4; o >= 1; o >>= 1) {
#pragma unroll
        for (int k = 0; k < 7; k++)
            acc[k] += __shfl_down_sync(FULLM, acc[k], o, 8);
        wsum += __shfl_down_sync(FULLM, wsum, o, 8);
    }

    if (ll == 0) {
        float inv = 1.f / (wsum + 1e-9f);
        float v[N_CLS];
        float m = -1e30f;
#pragma unroll
        for (int k = 0; k < N_CLS; k++) {
            v[k] = acc[k] * inv;
            m = fmaxf(m, v[k]);
        }
        float sx = 0.f;
#pragma unroll
        for (int k = 0; k < N_CLS; k++) sx += __expf(v[k] - m);
        float ls = m + __logf(sx);
        float* h2p = H2out + (size_t)gid * N_CLS;
        float* lpp = logp + (size_t)gid * N_CLS;
#pragma unroll
        for (int k = 0; k < N_CLS; k++) {
            h2p[k] = v[k];
            lpp[k] = v[k] - ls;
        }
    }
}

// ---------------- launch ---------------------------------------------------
// Enqueue: zero(1,s1) eoff(2,main) count(3,s1) gemm1(4,main=capture slot)
// p1l1(5,main) scans+scatter(s1) join tail.
extern "C" void kernel_launch(void* const* d_in, const int* in_sizes, int n_in,
                              void* d_out, int out_size)
{
    const float* H   = (const float*)d_in[0];
    const float* W1  = (const float*)d_in[1];
    const float* a11 = (const float*)d_in[2];
    const float* a21 = (const float*)d_in[3];
    const float* W2  = (const float*)d_in[4];
    const float* a12 = (const float*)d_in[5];
    const float* a22 = (const float*)d_in[6];
    const int* node_idx = (const int*)d_in[7];
    const int* edge_idx = (const int*)d_in[8];

    float* out  = (float*)d_out;
    float* logp = out;                                              // [N, 7]
    float* H1   = out + (size_t)N_NODES * N_CLS;                    // [N, 16]
    float* H2   = out + (size_t)N_NODES * (N_CLS + D_HID);          // [N, 7]

    static cudaStream_t s1 = nullptr;
    static cudaEvent_t evF = nullptr, evJ = nullptr;
    if (s1 == nullptr) {
        cudaStreamCreateWithFlags(&s1, cudaStreamNonBlocking);
        cudaEventCreateWithFlags(&evF, cudaEventDisableTiming);
        cudaEventCreateWithFlags(&evJ, cudaEventDisableTiming);
    }

    // fork
    cudaEventRecord(evF, 0);
    cudaStreamWaitEvent(s1, evF, 0);

    // side: zero counts
    k_zero<<<(N_NODES + 255) / 256, 256, 0, s1>>>();

    // main: edge offsets
    k_eoff<<<(N_EDGES + 255) / 256, 256>>>(edge_idx);

    // side: count
    k_count<<<(NNZ / 4 + 255) / 256, 256, 0, s1>>>((const int4*)node_idx);

    // main: FFMA2 gemm1, 32-col chunks (4th enqueued -> ncu capture)
    k_gemm1<<<(N_NODES + 127) / 128, 128>>>(H, W1, a11, a21);

    // main: phase1 L1
    k_phase1_l1<<<N_EDGES / 32, 256>>>(node_idx, a21 + D_HID);

    // side: rest of CSR build
    k_scan1<<<100, 1024, 0, s1>>>();
    k_scan2<<<1, 128, 0, s1>>>();
    k_scan3<<<100, 1024, 0, s1>>>();
    k_scatter<<<(NNZ / 4 + 255) / 256, 256, 0, s1>>>((const int4*)node_idx,
                                                     (const int4*)edge_idx);
    cudaEventRecord(evJ, s1);

    // join: node CSR needed from here on
    cudaStreamWaitEvent(0, evJ, 0);
    k_phase2_l1<<<N_NODES / 32, 256>>>(H1, W2, a12, a22);
    k_phase1_l2<<<N_EDGES / 32, 256>>>(node_idx, a22 + N_CLS);
    k_phase2_l2<<<N_NODES / 32, 256>>>(H2, logp);
}

// round 16
// speedup vs baseline: 1.3511x; 1.0195x over previous
#include <cuda_runtime.h>
#include <cuda_fp16.h>
#include <cstdint>
#include <cstddef>

#define N_NODES 100000
#define N_EDGES 100000
#define NNZ     3200000
#define D_IN    512
#define D_HID   16
#define N_CLS   7
#define LOG2E   1.4426950408889634f
#define FULLM   0xffffffffu

// ---------------- scratch (device globals) ---------------------------------
__device__ __align__(128) __half g_hu1h[(size_t)N_NODES * 16]; // L1 node rows: h*u fp16 (32B)
__device__ float  g_u1[N_NODES];                               // u fp32
__device__ __align__(128) __half g_e1h[(size_t)N_EDGES * 16];  // L1 edge rows: e fp16 (32B)
__device__ float  g_t2e1[N_EDGES];                             // (e.a2hi)*log2e fp32
__device__ __align__(128) __half g_hu2h[(size_t)N_NODES * 8];  // L2 node rows: [h2*u (7), u] (16B)
__device__ __align__(128) __half g_e2h[(size_t)N_EDGES * 8];   // L2 edge rows: [e2 (7), t2*log2e] (16B)
__device__ float  g_t1[N_NODES];                               // (h.a2lo)*log2e
__device__ int    g_eoff[N_EDGES + 1];
__device__ int    g_cnt[N_NODES];
__device__ int    g_noff[N_NODES + 1];
__device__ int    g_cur[N_NODES];
__device__ int    g_pedge[NNZ];
__device__ int    g_bsum[128];
__device__ int    g_bpre[128];

__device__ __forceinline__ float lrelu(float v) { return v > 0.f ? v : 0.2f * v; }

// ---- packed f32x2 helpers --------------------------------------------------
__device__ __forceinline__ unsigned long long splat2(float x) {
    unsigned long long r;
    unsigned int u = __float_as_uint(x);
    asm("mov.b64 %0, {%1, %1};" : "=l"(r) : "r"(u));
    return r;
}
__device__ __forceinline__ unsigned long long ffma2(unsigned long long a,
                                                    unsigned long long b,
                                                    unsigned long long c) {
    unsigned long long d;
    asm("fma.rn.f32x2 %0, %1, %2, %3;" : "=l"(d) : "l"(a), "l"(b), "l"(c));
    return d;
}
__device__ __forceinline__ void unpack2(unsigned long long v, float& lo, float& hi) {
    unsigned int a, b;
    asm("mov.b64 {%0, %1}, %2;" : "=r"(a), "=r"(b) : "l"(v));
    lo = __uint_as_float(a);
    hi = __uint_as_float(b);
}
__device__ __forceinline__ void acc8(const uint4& v, float* acc, float w) {
    float2 f0 = __half22float2(*(const __half2*)&v.x);
    float2 f1 = __half22float2(*(const __half2*)&v.y);
    float2 f2 = __half22float2(*(const __half2*)&v.z);
    float2 f3 = __half22float2(*(const __half2*)&v.w);
    acc[0] += w * f0.x; acc[1] += w * f0.y;
    acc[2] += w * f1.x; acc[3] += w * f1.y;
    acc[4] += w * f2.x; acc[5] += w * f2.y;
    acc[6] += w * f3.x; acc[7] += w * f3.y;
}
__device__ __forceinline__ void add8(const uint4& v, float* acc) {
    float2 f0 = __half22float2(*(const __half2*)&v.x);
    float2 f1 = __half22float2(*(const __half2*)&v.y);
    float2 f2 = __half22float2(*(const __half2*)&v.z);
    float2 f3 = __half22float2(*(const __half2*)&v.w);
    acc[0] += f0.x; acc[1] += f0.y;
    acc[2] += f1.x; acc[3] += f1.y;
    acc[4] += f2.x; acc[5] += f2.y;
    acc[6] += f3.x; acc[7] += f3.y;
}
__device__ __forceinline__ uint4 pack8(const float* e) {
    __half2 p[4];
    p[0] = __float22half2_rn(make_float2(e[0], e[1]));
    p[1] = __float22half2_rn(make_float2(e[2], e[3]));
    p[2] = __float22half2_rn(make_float2(e[4], e[5]));
    p[3] = __float22half2_rn(make_float2(e[6], e[7]));
    return *(uint4*)p;
}

// ---------------- k_zero ----------------------------------------------------
__global__ void k_zero()
{
    int n = blockIdx.x * blockDim.x + threadIdx.x;
    if (n < N_NODES) g_cnt[n] = 0;
}

// ---------------- edge offsets ---------------------------------------------
__global__ void k_eoff(const int* __restrict__ edge_idx)
{
    int e = blockIdx.x * blockDim.x + threadIdx.x;
    if (e >= N_EDGES) return;
    int lo = 0, hi = NNZ;
    while (lo < hi) {
        int m = (lo + hi) >> 1;
        if (__ldg(edge_idx + m) < e) lo = m + 1; else hi = m;
    }
    g_eoff[e] = lo;
    if (e == 0) g_eoff[N_EDGES] = NNZ;
}

// ---------------- node CSR build (plain 4-wide; measured best) -------------
__global__ void k_count(const int4* __restrict__ node_idx4)
{
    int i = blockIdx.x * blockDim.x + threadIdx.x;
    if (i >= NNZ / 4) return;
    int4 v = node_idx4[i];
    atomicAdd(&g_cnt[v.x], 1);
    atomicAdd(&g_cnt[v.y], 1);
    atomicAdd(&g_cnt[v.z], 1);
    atomicAdd(&g_cnt[v.w], 1);
}
__global__ void k_scan1()
{
    __shared__ int sp[1024];
    int t = threadIdx.x, b = blockIdx.x;
    int idx = b * 1000 + t;
    int v = (t < 1000) ? g_cnt[idx] : 0;
    sp[t] = v;
    __syncthreads();
    for (int o = 1; o < 1024; o <<= 1) {
        int u = (t >= o) ? sp[t - o] : 0;
        __syncthreads();
        sp[t] += u;
        __syncthreads();
    }
    if (t < 1000) g_noff[idx] = sp[t] - v;
    if (t == 1023) g_bsum[b] = sp[1023];
}
__global__ void k_scan2()
{
    __shared__ int sp[128];
    int t = threadIdx.x;
    int v = (t < 100) ? g_bsum[t] : 0;
    sp[t] = v;
    __syncthreads();
    for (int o = 1; o < 128; o <<= 1) {
        int u = (t >= o) ? sp[t - o] : 0;
        __syncthreads();
        sp[t] += u;
        __syncthreads();
    }
    if (t < 100) g_bpre[t] = sp[t] - v;
}
__global__ void k_scan3()
{
    int t = threadIdx.x, b = blockIdx.x;
    int idx = b * 1000 + t;
    if (t < 1000) {
        int o = g_noff[idx] + g_bpre[b];
        g_noff[idx] = o;
        g_cur[idx] = o;
    }
    if (idx == 0) g_noff[N_NODES] = NNZ;
}
__global__ void k_scatter(const int4* __restrict__ node_idx4, const int4* __restrict__ edge_idx4)
{
    int i = blockIdx.x * blockDim.x + threadIdx.x;
    if (i >= NNZ / 4) return;
    int4 nd = node_idx4[i];
    int4 ed = edge_idx4[i];
    g_pedge[atomicAdd(&g_cur[nd.x], 1)] = ed.x;
    g_pedge[atomicAdd(&g_cur[nd.y], 1)] = ed.y;
    g_pedge[atomicAdd(&g_cur[nd.z], 1)] = ed.z;
    g_pedge[atomicAdd(&g_cur[nd.w], 1)] = ed.w;
}

// ---------------- GEMM1 (FFMA2, 32-col chunks, occupancy-bounded) ----------
__global__ void __launch_bounds__(128, 9)
k_gemm1(const float* __restrict__ X, const float* __restrict__ W,
        const float* __restrict__ a1, const float* __restrict__ a2lo)
{
    __shared__ __align__(16) float sX[128 * 33];   // 16.9KB; reused as D stage (stride 17)
    __shared__ __align__(16) float sW[32 * 16];    // 2KB
    const int t = threadIdx.x;
    const int nbase = blockIdx.x * 128;
    const int ng = t >> 2, jg = t & 3;

    unsigned long long acc[4][2];
#pragma unroll
    for (int a = 0; a < 4; a++) { acc[a][0] = 0ull; acc[a][1] = 0ull; }

    for (int ck = 0; ck < D_IN; ck += 32) {
        // load X chunk: 128 rows x 32 cols, staged in 2 batches of 4 float4
#pragma unroll
        for (int half = 0; half < 2; half++) {
            float4 tmp[4];
#pragma unroll
            for (int it = 0; it < 4; it++) {
                int q = t + (half * 4 + it) * 128;
                int row = q >> 3, fc = q & 7;
                int n = nbase + row;
                tmp[it] = make_float4(0.f, 0.f, 0.f, 0.f);
                if (n < N_NODES)
                    tmp[it] = *(const float4*)(X + (size_t)n * D_IN + ck + fc * 4);
            }
#pragma unroll
            for (int it = 0; it < 4; it++) {
                int q = t + (half * 4 + it) * 128;
                int row = q >> 3, fc = q & 7;
                int b = row * 33 + fc * 4;
                sX[b] = tmp[it].x; sX[b + 1] = tmp[it].y;
                sX[b + 2] = tmp[it].z; sX[b + 3] = tmp[it].w;
            }
        }
        // load W chunk: 32 x 16 (1 float4 per thread)
        {
            float4 v = *(const float4*)(W + ck * 16 + t * 4);
            *(float4*)(sW + t * 4) = v;
        }
        __syncthreads();
#pragma unroll
        for (int c = 0; c < 32; c++) {
            unsigned long long wp0 = *(const unsigned long long*)(sW + c * 16 + jg * 4);
            unsigned long long wp1 = *(const unsigned long long*)(sW + c * 16 + jg * 4 + 2);
#pragma unroll
            for (int a = 0; a < 4; a++) {
                unsigned long long xs = splat2(sX[(ng * 4 + a) * 33 + c]);
                acc[a][0] = ffma2(xs, wp0, acc[a][0]);
                acc[a][1] = ffma2(xs, wp1, acc[a][1]);
            }
        }
        __syncthreads();
    }

#pragma unroll
    for (int a = 0; a < 4; a++) {
        float v0, v1, v2, v3;
        unpack2(acc[a][0], v0, v1);
        unpack2(acc[a][1], v2, v3);
        int j = jg * 4;
        int srow = (ng * 4 + a) * 17;
        sX[srow + j] = v0; sX[srow + j + 1] = v1;
        sX[srow + j + 2] = v2; sX[srow + j + 3] = v3;
    }
    __syncthreads();
    {
        int n = nbase + t;
        if (n < N_NODES) {
            float hv[16];
            float uu = 0.f, tt = 0.f;
#pragma unroll
            for (int j = 0; j < D_HID; j++) {
                hv[j] = sX[t * 17 + j];
                uu += hv[j] * __ldg(a1 + j);
                tt += hv[j] * __ldg(a2lo + j);
            }
            float u = exp2f(lrelu(uu * LOG2E));
            float e0[8], e1[8];
#pragma unroll
            for (int j = 0; j < 8; j++) { e0[j] = hv[j] * u; e1[j] = hv[8 + j] * u; }
            __half* dst = g_hu1h + (size_t)n * 16;
            *(uint4*)dst = pack8(e0);
            *(uint4*)(dst + 8) = pack8(e1);
            g_u1[n] = u;
            g_t1[n] = tt * LOG2E;
        }
    }
}

// ---------------- phase 1, layer 1: 8-lane group per edge, unroll x4 -------
__global__ void k_phase1_l1(const int* __restrict__ node_idx, const float* __restrict__ a2hi)
{
    int gid = (blockIdx.x * blockDim.x + threadIdx.x) >> 3;
    if (gid >= N_EDGES) return;
    const int lane = threadIdx.x & 31;
    const int ll = lane & 7;
    const int r = ll & 1;
    int s = __ldg(g_eoff + gid), epos = __ldg(g_eoff + gid + 1);

    float acc[8];
#pragma unroll
    for (int k = 0; k < 8; k++) acc[k] = 0.f;
    float usum = 0.f;

    int i = s + (ll >> 1);
    for (; i + 12 < epos; i += 16) {
        int nd0 = __ldg(node_idx + i);
        int nd1 = __ldg(node_idx + i + 4);
        int nd2 = __ldg(node_idx + i + 8);
        int nd3 = __ldg(node_idx + i + 12);
        uint4 v0 = *((const uint4*)(g_hu1h + (size_t)nd0 * 16) + r);
        uint4 v1 = *((const uint4*)(g_hu1h + (size_t)nd1 * 16) + r);
        uint4 v2 = *((const uint4*)(g_hu1h + (size_t)nd2 * 16) + r);
        uint4 v3 = *((const uint4*)(g_hu1h + (size_t)nd3 * 16) + r);
        add8(v0, acc); add8(v1, acc); add8(v2, acc); add8(v3, acc);
        if (r == 0) usum += __ldg(g_u1 + nd0) + __ldg(g_u1 + nd1)
                          + __ldg(g_u1 + nd2) + __ldg(g_u1 + nd3);
    }
    for (; i < epos; i += 4) {
        int nd = __ldg(node_idx + i);
        uint4 v = *((const uint4*)(g_hu1h + (size_t)nd * 16) + r);
        add8(v, acc);
        if (r == 0) usum += __ldg(g_u1 + nd);
    }
#pragma unroll
    for (int o = 4; o >= 2; o >>= 1)
#pragma unroll
        for (int k = 0; k < 8; k++)
            acc[k] += __shfl_down_sync(FULLM, acc[k], o, 8);
    usum += __shfl_down_sync(FULLM, usum, 4, 8);
    usum += __shfl_down_sync(FULLM, usum, 2, 8);
    usum = __shfl_sync(FULLM, usum, 0, 8);
    float inv = 1.f / (usum + 1e-9f);

    float t2p = 0.f;
    if (ll < 2) {
        float e8[8];
#pragma unroll
        for (int k = 0; k < 8; k++) {
            e8[k] = acc[k] * inv;
            t2p += e8[k] * __ldg(a2hi + r * 8 + k);
        }
        *((uint4*)(g_e1h + (size_t)gid * 16) + r) = pack8(e8);
    }
    t2p += __shfl_xor_sync(FULLM, t2p, 1);
    if (ll == 0) g_t2e1[gid] = t2p * LOG2E;
}

// ---------------- phase 2, layer 1 + fused gemm2 epilogue, unroll x4 -------
__global__ void k_phase2_l1(float* __restrict__ H1out, const float* __restrict__ W2,
                            const float* __restrict__ a1, const float* __restrict__ a2lo)
{
    int gid = (blockIdx.x * blockDim.x + threadIdx.x) >> 3;
    if (gid >= N_NODES) return;
    const int lane = threadIdx.x & 31;
    const int ll = lane & 7;
    const int r = ll & 1;
    int s = __ldg(g_noff + gid), e = __ldg(g_noff + gid + 1);
    float t1n = __ldg(g_t1 + gid);

    float acc[8];
#pragma unroll
    for (int k = 0; k < 8; k++) acc[k] = 0.f;
    float wsum = 0.f;

    int i = s + (ll >> 1);
    for (; i + 12 < e; i += 16) {
        int ed0 = __ldg(g_pedge + i);
        int ed1 = __ldg(g_pedge + i + 4);
        int ed2 = __ldg(g_pedge + i + 8);
        int ed3 = __ldg(g_pedge + i + 12);
        float t20 = __ldg(g_t2e1 + ed0);
        float t21 = __ldg(g_t2e1 + ed1);
        float t22 = __ldg(g_t2e1 + ed2);
        float t23 = __ldg(g_t2e1 + ed3);
        uint4 v0 = *((const uint4*)(g_e1h + (size_t)ed0 * 16) + r);
        uint4 v1 = *((const uint4*)(g_e1h + (size_t)ed1 * 16) + r);
        uint4 v2 = *((const uint4*)(g_e1h + (size_t)ed2 * 16) + r);
        uint4 v3 = *((const uint4*)(g_e1h + (size_t)ed3 * 16) + r);
        float wv0 = exp2f(lrelu(t1n + t20));
        float wv1 = exp2f(lrelu(t1n + t21));
        float wv2 = exp2f(lrelu(t1n + t22));
        float wv3 = exp2f(lrelu(t1n + t23));
        if (r == 1) wsum += (wv0 + wv1) + (wv2 + wv3);
        acc8(v0, acc, wv0); acc8(v1, acc, wv1);
        acc8(v2, acc, wv2); acc8(v3, acc, wv3);
    }
    for (; i < e; i += 4) {
        int ed = __ldg(g_pedge + i);
        float wv = exp2f(lrelu(t1n + __ldg(g_t2e1 + ed)));
        if (r == 1) wsum += wv;
        uint4 v = *((const uint4*)(g_e1h + (size_t)ed * 16) + r);
        acc8(v, acc, wv);
    }
#pragma unroll
    for (int o = 4; o >= 2; o >>= 1)
#pragma unroll
        for (int k = 0; k < 8; k++)
            acc[k] += __shfl_down_sync(FULLM, acc[k], o, 8);
    wsum += __shfl_down_sync(FULLM, wsum, 4, 8);
    wsum += __shfl_down_sync(FULLM, wsum, 2, 8);
    wsum = __shfl_sync(FULLM, wsum, 1, 8);
    float inv = 1.f / (wsum + 1e-9f);

    float hk[8];
#pragma unroll
    for (int k = 0; k < 8; k++) hk[k] = acc[k] * inv;
    if (ll < 2) {
        *(float4*)(H1out + (size_t)gid * 16 + r * 8) =
            make_float4(hk[0], hk[1], hk[2], hk[3]);
        *(float4*)(H1out + (size_t)gid * 16 + r * 8 + 4) =
            make_float4(hk[4], hk[5], hk[6], hk[7]);
    }

    float h1a = 0.f, h1b = 0.f;
#pragma unroll
    for (int k = 0; k < 8; k++) {
        float t0 = __shfl_sync(FULLM, hk[k], 0, 8);
        float t1v = __shfl_sync(FULLM, hk[k], 1, 8);
        if (ll == k) { h1a = t0; h1b = t1v; }
    }
    float xa = h1a > 0.f ? h1a : expm1f(h1a);
    float xb = h1b > 0.f ? h1b : expm1f(h1b);
    float sarr[N_CLS];
#pragma unroll
    for (int jj = 0; jj < N_CLS; jj++) {
        float p = xa * __ldg(W2 + ll * N_CLS + jj) + xb * __ldg(W2 + (ll + 8) * N_CLS + jj);
        p += __shfl_down_sync(FULLM, p, 4, 8);
        p += __shfl_down_sync(FULLM, p, 2, 8);
        p += __shfl_down_sync(FULLM, p, 1, 8);
        sarr[jj] = p;
    }
    if (ll == 0) {
        float uu = 0.f, tt = 0.f;
#pragma unroll
        for (int jj = 0; jj < N_CLS; jj++) {
            uu += sarr[jj] * __ldg(a1 + jj);
            tt += sarr[jj] * __ldg(a2lo + jj);
        }
        float u = exp2f(lrelu(uu * LOG2E));
        float e8[8];
#pragma unroll
        for (int jj = 0; jj < N_CLS; jj++) e8[jj] = sarr[jj] * u;
        e8[7] = u;
        *(uint4*)(g_hu2h + (size_t)gid * 8) = pack8(e8);
        g_t1[gid] = tt * LOG2E;
    }
}

// ---------------- phase 1, layer 2: unroll x2 ------------------------------
__global__ void k_phase1_l2(const int* __restrict__ node_idx, const float* __restrict__ a2hi)
{
    int gid = (blockIdx.x * blockDim.x + threadIdx.x) >> 3;
    if (gid >= N_EDGES) return;
    const int ll = threadIdx.x & 7;
    int s = __ldg(g_eoff + gid), epos = __ldg(g_eoff + gid + 1);

    float acc[8];
#pragma unroll
    for (int k = 0; k < 8; k++) acc[k] = 0.f;

    int i = s + ll;
    for (; i + 8 < epos; i += 16) {
        int nd0 = __ldg(node_idx + i);
        int nd1 = __ldg(node_idx + i + 8);
        uint4 v0 = *(const uint4*)(g_hu2h + (size_t)nd0 * 8);
        uint4 v1 = *(const uint4*)(g_hu2h + (size_t)nd1 * 8);
        add8(v0, acc);
        add8(v1, acc);
    }
    if (i < epos) {
        int nd = __ldg(node_idx + i);
        uint4 v = *(const uint4*)(g_hu2h + (size_t)nd * 8);
        add8(v, acc);
    }
#pragma unroll
    for (int o = 4; o >= 1; o >>= 1)
#pragma unroll
        for (int k = 0; k < 8; k++)
            acc[k] += __shfl_down_sync(FULLM, acc[k], o, 8);

    if (ll == 0) {
        float inv = 1.f / (acc[7] + 1e-9f);
        float e8[8];
        float t2 = 0.f;
#pragma unroll
        for (int k = 0; k < 7; k++) {
            e8[k] = acc[k] * inv;
            t2 += e8[k] * __ldg(a2hi + k);
        }
        e8[7] = t2 * LOG2E;
        *(uint4*)(g_e2h + (size_t)gid * 8) = pack8(e8);
    }
}

// ---------------- phase 2, layer 2 + fused log_softmax, unroll x2 ----------
__global__ void k_phase2_l2(float* __restrict__ H2out, float* __restrict__ logp)
{
    int gid = (blockIdx.x * blockDim.x + threadIdx.x) >> 3;
    if (gid >= N_NODES) return;
    const int ll = threadIdx.x & 7;
    int s = __ldg(g_noff + gid), e = __ldg(g_noff + gid + 1);
    float t1n = __ldg(g_t1 + gid);

    float acc[8];
#pragma unroll
    for (int k = 0; k < 8; k++) acc[k] = 0.f;
    float wsum = 0.f;

    int i = s + ll;
    for (; i + 8 < e; i += 16) {
        int ed0 = __ldg(g_pedge + i);
        int ed1 = __ldg(g_pedge + i + 8);
        uint4 v0 = *(const uint4*)(g_e2h + (size_t)ed0 * 8);
        uint4 v1 = *(const uint4*)(g_e2h + (size_t)ed1 * 8);
        float t20 = __half2float(((const __half*)&v0.w)[1]);
        float t21 = __half2float(((const __half*)&v1.w)[1]);
        float wv0 = exp2f(lrelu(t1n + t20));
        float wv1 = exp2f(lrelu(t1n + t21));
        wsum += wv0 + wv1;
        acc8(v0, acc, wv0);
        acc8(v1, acc, wv1);
    }
    if (i < e) {
        int ed = __ldg(g_pedge + i);
        uint4 v = *(const uint4*)(g_e2h + (size_t)ed * 8);
        float t2 = __half2float(((const __half*)&v.w)[1]);
        float wv = exp2f(lrelu(t1n + t2));
        wsum += wv;
        acc8(v, acc, wv);
    }
#pragma unroll
    for (int o = 4; o >= 1; o >>= 1) {
#pragma unroll
        for (int k = 0; k < 7; k++)
            acc[k] += __shfl_down_sync(FULLM, acc[k], o, 8);
        wsum += __shfl_down_sync(FULLM, wsum, o, 8);
    }

    if (ll == 0) {
        float inv = 1.f / (wsum + 1e-9f);
        float v[N_CLS];
        float m = -1e30f;
#pragma unroll
        for (int k = 0; k < N_CLS; k++) {
            v[k] = acc[k] * inv;
            m = fmaxf(m, v[k]);
        }
        float sx = 0.f;
#pragma unroll
        for (int k = 0; k < N_CLS; k++) sx += __expf(v[k] - m);
        float ls = m + __logf(sx);
        float* h2p = H2out + (size_t)gid * N_CLS;
        float* lpp = logp + (size_t)gid * N_CLS;
#pragma unroll
        for (int k = 0; k < N_CLS; k++) {
            h2p[k] = v[k];
            lpp[k] = v[k] - ls;
        }
    }
}

// ---------------- launch ---------------------------------------------------
// 3-way fork: main = gemm1 -> p1l1 -> (join) tail
//             s1   = zero -> count -> scans -> scatter   (node CSR)
//             s2   = eoff                                 (edge offsets)
// Enqueue order keeps gemm1 in the 4th slot (ncu capture target).
extern "C" void kernel_launch(void* const* d_in, const int* in_sizes, int n_in,
                              void* d_out, int out_size)
{
    const float* H   = (const float*)d_in[0];
    const float* W1  = (const float*)d_in[1];
    const float* a11 = (const float*)d_in[2];
    const float* a21 = (const float*)d_in[3];
    const float* W2  = (const float*)d_in[4];
    const float* a12 = (const float*)d_in[5];
    const float* a22 = (const float*)d_in[6];
    const int* node_idx = (const int*)d_in[7];
    const int* edge_idx = (const int*)d_in[8];

    float* out  = (float*)d_out;
    float* logp = out;                                              // [N, 7]
    float* H1   = out + (size_t)N_NODES * N_CLS;                    // [N, 16]
    float* H2   = out + (size_t)N_NODES * (N_CLS + D_HID);          // [N, 7]

    static cudaStream_t s1 = nullptr, s2 = nullptr;
    static cudaEvent_t evF = nullptr, evE = nullptr, evJ = nullptr;
    if (s1 == nullptr) {
        cudaStreamCreateWithFlags(&s1, cudaStreamNonBlocking);
        cudaStreamCreateWithFlags(&s2, cudaStreamNonBlocking);
        cudaEventCreateWithFlags(&evF, cudaEventDisableTiming);
        cudaEventCreateWithFlags(&evE, cudaEventDisableTiming);
        cudaEventCreateWithFlags(&evJ, cudaEventDisableTiming);
    }

    // fork
    cudaEventRecord(evF, 0);
    cudaStreamWaitEvent(s1, evF, 0);
    cudaStreamWaitEvent(s2, evF, 0);

    // side 1: zero counts
    k_zero<<<(N_NODES + 255) / 256, 256, 0, s1>>>();

    // side 2: edge offsets
    k_eoff<<<(N_EDGES + 255) / 256, 256, 0, s2>>>(edge_idx);
    cudaEventRecord(evE, s2);

    // side 1: count
    k_count<<<(NNZ / 4 + 255) / 256, 256, 0, s1>>>((const int4*)node_idx);

    // main: gemm1 (4th enqueued -> ncu capture)
    k_gemm1<<<(N_NODES + 127) / 128, 128>>>(H, W1, a11, a21);

    // main: phase1 L1 (needs eoff)
    cudaStreamWaitEvent(0, evE, 0);
    k_phase1_l1<<<N_EDGES / 32, 256>>>(node_idx, a21 + D_HID);

    // side 1: rest of CSR build
    k_scan1<<<100, 1024, 0, s1>>>();
    k_scan2<<<1, 128, 0, s1>>>();
    k_scan3<<<100, 1024, 0, s1>>>();
    k_scatter<<<(NNZ / 4 + 255) / 256, 256, 0, s1>>>((const int4*)node_idx,
                                                     (const int4*)edge_idx);
    cudaEventRecord(evJ, s1);

    // join: node CSR needed from here on
    cudaStreamWaitEvent(0, evJ, 0);
    k_phase2_l1<<<N_NODES / 32, 256>>>(H1, W2, a12, a22);
    k_phase1_l2<<<N_EDGES / 32, 256>>>(node_idx, a22 + N_CLS);   // also needs eoff (already waited)
    k_phase2_l2<<<N_NODES / 32, 256>>>(H2, logp);
}